// round 10
// baseline (speedup 1.0000x reference)
#include <cuda_runtime.h>
#include <cstdint>

#define NN 50000
#define NE 500000
#define DIM 160
#define BOND 14
#define WS 88   // k_mma padded k-stride (bf16)

// ---------------- scratch ----------------
__device__ int   g_src[NE];
__device__ int   g_dst[NE];
__device__ float g_P [NN * DIM];
__device__ unsigned short g_Hhi[NE * DIM], g_Hlo[NE * DIM];
__device__ unsigned short g_Ghi[NE * DIM], g_Glo[NE * DIM];
__device__ unsigned short g_EAhi[NE * 16], g_EAlo[NE * 16];
__device__ float g_S0[NN * DIM];
__device__ float g_S1[NN * DIM];
__device__ float g_M1[NN * DIM];
__device__ float g_T [NN * DIM];
__device__ unsigned short g_Wih[160 * 176], g_Wil[160 * 176];
__device__ unsigned short g_Whh[160 * 160], g_Whl[160 * 160];
__device__ unsigned short g_Woh[160 * 320], g_Wol[160 * 320];

// ---------------- helpers ----------------
__device__ __forceinline__ uint32_t cvta_s(const void* p) {
    uint32_t r;
    asm("{ .reg .u64 t; cvta.to.shared.u64 t, %1; cvt.u32.u64 %0, t; }" : "=r"(r) : "l"(p));
    return r;
}
__device__ __forceinline__ void ldsm4(uint32_t (&r)[4], uint32_t addr) {
    asm volatile("ldmatrix.sync.aligned.m8n8.x4.shared.b16 {%0,%1,%2,%3}, [%4];"
                 : "=r"(r[0]), "=r"(r[1]), "=r"(r[2]), "=r"(r[3]) : "r"(addr));
}
__device__ __forceinline__ void mma16816(float* c, const uint32_t (&a)[4],
                                         uint32_t b0, uint32_t b1) {
    asm volatile("mma.sync.aligned.m16n8k16.row.col.f32.bf16.bf16.f32 "
                 "{%0,%1,%2,%3},{%4,%5,%6,%7},{%8,%9},{%0,%1,%2,%3};"
                 : "+f"(c[0]), "+f"(c[1]), "+f"(c[2]), "+f"(c[3])
                 : "r"(a[0]), "r"(a[1]), "r"(a[2]), "r"(a[3]), "r"(b0), "r"(b1));
}
__device__ __forceinline__ void split2(float x, float y, uint32_t& hi2, uint32_t& lo2) {
    uint32_t ux = __float_as_uint(x), uy = __float_as_uint(y);
    hi2 = __byte_perm(ux, uy, 0x7632);
    float lx = x - __uint_as_float(ux & 0xffff0000u);
    float ly = y - __uint_as_float(uy & 0xffff0000u);
    asm("cvt.rn.bf16x2.f32 %0, %1, %2;" : "=r"(lo2) : "f"(ly), "f"(lx));
}
__device__ __forceinline__ float2 recon2(uint32_t hi2, uint32_t lo2) {
    float2 r;
    r.x = __uint_as_float(hi2 << 16) + __uint_as_float(lo2 << 16);
    r.y = __uint_as_float(hi2 & 0xffff0000u) + __uint_as_float(lo2 & 0xffff0000u);
    return r;
}
__device__ __forceinline__ void cp16(uint32_t dst, const void* src) {
    asm volatile("cp.async.cg.shared.global [%0], [%1], 16;" :: "r"(dst), "l"(src));
}
__device__ __forceinline__ void redv4(float* p, float4 v) {
    asm volatile("red.global.add.v4.f32 [%0], {%1,%2,%3,%4};"
                 :: "l"(p), "f"(v.x), "f"(v.y), "f"(v.z), "f"(v.w) : "memory");
}
__device__ __forceinline__ void prefetchL2(const void* p) {
    asm volatile("prefetch.global.L2 [%0];" :: "l"(p));
}

// ---------------- prep ----------------
__global__ void k_prep(const void* ei, const float* __restrict__ ea,
                       float* S0, float* S1, float* M1) {
    __shared__ int s64;
    if (threadIdx.x < 32) {
        const unsigned long long* p = (const unsigned long long*)ei;
        int bad = 0;
        for (int j = threadIdx.x; j < 1024; j += 32)
            if (p[j] >= (unsigned long long)NN) bad = 1;
        unsigned m = __ballot_sync(0xffffffffu, bad);
        if (threadIdx.x == 0) s64 = (m == 0u);
    }
    __syncthreads();
    const int is64 = s64;
    const int gstride = gridDim.x * blockDim.x;
    int g = blockIdx.x * blockDim.x + threadIdx.x;
    for (int i = g; i < NE; i += gstride) {
        if (is64) {
            const long long* p = (const long long*)ei;
            g_src[i] = (int)p[i];
            g_dst[i] = (int)p[NE + i];
        } else {
            const int* p = (const int*)ei;
            g_src[i] = p[i];
            g_dst[i] = p[NE + i];
        }
    }
    const int nz = NN * DIM / 4;
    float4 z = make_float4(0.f, 0.f, 0.f, 0.f);
    for (int i = g; i < nz; i += gstride) {
        reinterpret_cast<float4*>(S0)[i] = z;
        reinterpret_cast<float4*>(S1)[i] = z;
        reinterpret_cast<float4*>(M1)[i] = z;
    }
    uint32_t* eh = (uint32_t*)g_EAhi;
    uint32_t* el = (uint32_t*)g_EAlo;
    for (int i = g; i < NE * 8; i += gstride) {
        int e = i >> 3, c2 = (i & 7) << 1;
        float2 f = (c2 < BOND) ? *(const float2*)(ea + (size_t)e * BOND + c2)
                               : make_float2(0.f, 0.f);
        uint32_t h2, l2;
        split2(f.x, f.y, h2, l2);
        eh[i] = h2;
        el[i] = l2;
    }
}

// ---------------- weight split ----------------
__global__ void k_wsplit_all(const float* __restrict__ wi, const float* __restrict__ wh,
                             const float* __restrict__ wo) {
    int i = blockIdx.x * blockDim.x + threadIdx.x;
    const int nWi = 160 * 176, nWh = 160 * 160, nWo = 160 * 320;
    float f;
    unsigned short* hi;
    unsigned short* lo;
    int oi;
    if (i < nWi) {
        int h = i / 176, c = i - h * 176;
        f = (c < 174) ? wi[h * 174 + c] : 0.f;
        hi = g_Wih; lo = g_Wil; oi = i;
    } else if (i < nWi + nWh) {
        oi = i - nWi;
        f = wh[oi];
        hi = g_Whh; lo = g_Whl;
    } else if (i < nWi + nWh + nWo) {
        oi = i - nWi - nWh;
        f = wo[oi];
        hi = g_Woh; lo = g_Wol;
    } else return;
    uint32_t u = __float_as_uint(f);
    hi[oi] = (unsigned short)(u >> 16);
    float lf = f - __uint_as_float(u & 0xffff0000u);
    unsigned short ls;
    asm("cvt.rn.bf16.f32 %0, %1;" : "=h"(ls) : "f"(lf));
    lo[oi] = ls;
}

// ============ generic GEMM (P, T, out) — unchanged 128x160 tile ============
#define OFF_WHI 0
#define OFF_WLO (160 * WS * 2)
#define OFF_AHI (2 * 160 * WS * 2)
#define OFF_ALO (2 * 160 * WS * 2 + 128 * WS * 2)
#define MMA_SMEM (2 * 160 * WS * 2 + 2 * 128 * WS * 2)

#define MMA_BODY(aAhi, aAlo, bWhi, bWlo, ksteps, ws)                               \
    for (int ks = 0; ks < (ksteps); ks++) {                                        \
        const uint32_t ko = (uint32_t)ks * 32;                                     \
        uint32_t ah0[4], ah1[4], al0[4], al1[4];                                   \
        ldsm4(ah0, (aAhi) + ko);                                                   \
        ldsm4(ah1, (aAhi) + ko + 16 * (ws) * 2);                                   \
        ldsm4(al0, (aAlo) + ko);                                                   \
        ldsm4(al1, (aAlo) + ko + 16 * (ws) * 2);                                   \
        _Pragma("unroll")                                                          \
        for (int p = 0; p < 5; p++) {                                              \
            const uint32_t bo = ko + (uint32_t)p * (16 * (ws) * 2);                \
            uint32_t bh[4], bl[4];                                                 \
            ldsm4(bh, (bWhi) + bo);                                                \
            ldsm4(bl, (bWlo) + bo);                                                \
            mma16816(acc[2 * p],      ah0, bh[0], bh[1]);                          \
            mma16816(acc[2 * p],      ah0, bl[0], bl[1]);                          \
            mma16816(acc[2 * p],      al0, bh[0], bh[1]);                          \
            mma16816(acc[2 * p + 1],  ah0, bh[2], bh[3]);                          \
            mma16816(acc[2 * p + 1],  ah0, bl[2], bl[3]);                          \
            mma16816(acc[2 * p + 1],  al0, bh[2], bh[3]);                          \
            mma16816(acc[10 + 2 * p],     ah1, bh[0], bh[1]);                      \
            mma16816(acc[10 + 2 * p],     ah1, bl[0], bl[1]);                      \
            mma16816(acc[10 + 2 * p],     al1, bh[0], bh[1]);                      \
            mma16816(acc[10 + 2 * p + 1], ah1, bh[2], bh[3]);                      \
            mma16816(acc[10 + 2 * p + 1], ah1, bl[2], bl[3]);                      \
            mma16816(acc[10 + 2 * p + 1], al1, bh[2], bh[3]);                      \
        }                                                                          \
    }

__global__ __launch_bounds__(256, 2) void k_mma(
    const float* __restrict__ A0, int lda0, int klen0, int wk0,
    const float* __restrict__ A1, int lda1, int klen1, int wk1,
    int nph, int M,
    const unsigned short* __restrict__ Whi, const unsigned short* __restrict__ Wlo, int ldw,
    const float* __restrict__ bias, int dorelu,
    float* __restrict__ Cout)
{
    extern __shared__ char smem[];
    unsigned short* Whi_s = (unsigned short*)(smem + OFF_WHI);
    unsigned short* Wlo_s = (unsigned short*)(smem + OFF_WLO);
    unsigned short* Ahi_s = (unsigned short*)(smem + OFF_AHI);
    unsigned short* Alo_s = (unsigned short*)(smem + OFF_ALO);
    const uint32_t sbase = cvta_s(smem);

    const int tid = threadIdx.x;
    const int lane = tid & 31, wid = tid >> 5;
    const int warp_m = wid & 3, warp_n = wid >> 2;
    const int m0w = warp_m * 32, n0w = warp_n * 80;
    const int row0 = blockIdx.x * 128;

    const int arow = (lane & 7) + ((lane >> 3) & 1) * 8;
    const int acol = (lane >> 4) * 8;
    const uint32_t aAhi = sbase + OFF_AHI + (uint32_t)((m0w + arow) * WS + acol) * 2;
    const uint32_t aAlo = sbase + OFF_ALO + (uint32_t)((m0w + arow) * WS + acol) * 2;
    const int brow = (lane & 7) + ((lane >> 4) << 3);
    const int bcol = ((lane >> 3) & 1) * 8;
    const uint32_t bWhi = sbase + OFF_WHI + (uint32_t)((n0w + brow) * WS + bcol) * 2;
    const uint32_t bWlo = sbase + OFF_WLO + (uint32_t)((n0w + brow) * WS + bcol) * 2;

    float acc[20][4];
#pragma unroll
    for (int t = 0; t < 20; t++)
#pragma unroll
        for (int j = 0; j < 4; j++) acc[t][j] = 0.f;

    for (int ph = 0; ph < nph; ph++) {
        const float* A = (ph == 0) ? A0 : A1;
        const int lda  = (ph == 0) ? lda0 : lda1;
        const int klen = (ph == 0) ? klen0 : klen1;
        const int wk   = (ph == 0) ? wk0 : wk1;
        const int nch = (klen + 79) / 80;

        for (int c = 0; c < nch; c++) {
            const int k0g = c * 80;
            const int kc = min(80, klen - k0g);
            const bool cpW = (kc == 80) && ((ldw & 7) == 0) && (((wk + k0g) & 7) == 0);
            __syncthreads();

            if (cpW) {
                for (int idx = tid; idx < 160 * 10; idx += 256) {
                    int h = idx / 10, s = idx - h * 10;
                    uint32_t d = (uint32_t)((h * WS + s * 8) * 2);
                    const int gi = h * ldw + wk + k0g + s * 8;
                    cp16(sbase + OFF_WHI + d, Whi + gi);
                    cp16(sbase + OFF_WLO + d, Wlo + gi);
                }
                asm volatile("cp.async.commit_group;");
            } else {
                const int kpad = (kc + 15) & ~15;
                for (int idx = tid; idx < 160 * kpad; idx += 256) {
                    int h = idx / kpad, kk = idx - h * kpad;
                    unsigned short vh = 0, vl = 0;
                    if (kk < kc) {
                        int gi = h * ldw + wk + k0g + kk;
                        vh = Whi[gi]; vl = Wlo[gi];
                    }
                    Whi_s[h * WS + kk] = vh;
                    Wlo_s[h * WS + kk] = vl;
                }
            }

            if (kc == 80 && (lda & 3) == 0) {
                for (int idx = tid; idx < 128 * 20; idx += 256) {
                    int r = idx / 20, q = idx - r * 20;
                    int row = row0 + r;
                    float4 v = make_float4(0.f, 0.f, 0.f, 0.f);
                    if (row < M)
                        v = *reinterpret_cast<const float4*>(A + (size_t)row * lda + k0g + q * 4);
                    uint32_t h2a, l2a, h2b, l2b;
                    split2(v.x, v.y, h2a, l2a);
                    split2(v.z, v.w, h2b, l2b);
                    *(uint2*)&Ahi_s[r * WS + q * 4] = make_uint2(h2a, h2b);
                    *(uint2*)&Alo_s[r * WS + q * 4] = make_uint2(l2a, l2b);
                }
            } else {
                const int kpad = (kc + 15) & ~15;
                for (int idx = tid; idx < 128 * kpad; idx += 256) {
                    int r = idx / kpad, kk = idx - r * kpad;
                    int row = row0 + r;
                    float f = 0.f;
                    if (row < M && kk < kc) f = A[(size_t)row * lda + k0g + kk];
                    uint32_t u = __float_as_uint(f);
                    Ahi_s[r * WS + kk] = (unsigned short)(u >> 16);
                    float lf = f - __uint_as_float(u & 0xffff0000u);
                    unsigned short ls;
                    asm("cvt.rn.bf16.f32 %0, %1;" : "=h"(ls) : "f"(lf));
                    Alo_s[r * WS + kk] = ls;
                }
            }

            if (cpW) asm volatile("cp.async.wait_group 0;");
            __syncthreads();

            const int ksteps = ((kc + 15) & ~15) >> 4;
            MMA_BODY(aAhi, aAlo, bWhi, bWlo, ksteps, WS)
        }
    }

    __syncthreads();
    float* Cs = (float*)smem;
    {
        const int rf = m0w + (lane >> 2);
        const int cf = n0w + (lane & 3) * 2;
#pragma unroll
        for (int mt = 0; mt < 2; mt++)
#pragma unroll
            for (int half = 0; half < 2; half++) {
                int rr = rf + mt * 16 + half * 8;
#pragma unroll
                for (int nt = 0; nt < 10; nt++) {
                    float* pp = &Cs[rr * 164 + cf + nt * 8];
                    pp[0] = acc[mt * 10 + nt][half * 2 + 0];
                    pp[1] = acc[mt * 10 + nt][half * 2 + 1];
                }
            }
    }
    __syncthreads();

    for (int idx = tid; idx < 128 * 20; idx += 256) {
        int r = idx / 20, u = idx - r * 20;
        int row = row0 + r;
        if (row >= M) continue;
        float4 v0 = *reinterpret_cast<float4*>(&Cs[r * 164 + u * 8]);
        float4 v1 = *reinterpret_cast<float4*>(&Cs[r * 164 + u * 8 + 4]);
        if (bias) {
            float4 b0 = __ldg((const float4*)(bias + u * 8));
            float4 b1 = __ldg((const float4*)(bias + u * 8 + 4));
            v0.x += b0.x; v0.y += b0.y; v0.z += b0.z; v0.w += b0.w;
            v1.x += b1.x; v1.y += b1.y; v1.z += b1.z; v1.w += b1.w;
        }
        if (dorelu) {
            v0.x = fmaxf(v0.x, 0.f); v0.y = fmaxf(v0.y, 0.f);
            v0.z = fmaxf(v0.z, 0.f); v0.w = fmaxf(v0.w, 0.f);
            v1.x = fmaxf(v1.x, 0.f); v1.y = fmaxf(v1.y, 0.f);
            v1.z = fmaxf(v1.z, 0.f); v1.w = fmaxf(v1.w, 0.f);
        }
        float4* cp = (float4*)(Cout + (size_t)row * DIM + u * 8);
        cp[0] = v0; cp[1] = v1;
    }
}

// ============ N-split m16 micro-kernel pieces (128 rows x 80 cols per CTA) ============
// 8 warps, warp tile 16x80, acc[10][4].
#define MMA16_BODY(aAhi, aAlo, bWhi, bWlo, ksteps, ws)                             \
    for (int ks = 0; ks < (ksteps); ks++) {                                        \
        const uint32_t ko = (uint32_t)ks * 32;                                     \
        uint32_t ah[4], al[4];                                                     \
        ldsm4(ah, (aAhi) + ko);                                                    \
        ldsm4(al, (aAlo) + ko);                                                    \
        _Pragma("unroll")                                                          \
        for (int p = 0; p < 5; p++) {                                              \
            const uint32_t bo = ko + (uint32_t)p * (16 * (ws) * 2);                \
            uint32_t bh[4], bl[4];                                                 \
            ldsm4(bh, (bWhi) + bo);                                                \
            ldsm4(bl, (bWlo) + bo);                                                \
            mma16816(acc[2 * p],     ah, bh[0], bh[1]);                            \
            mma16816(acc[2 * p],     ah, bl[0], bl[1]);                            \
            mma16816(acc[2 * p],     al, bh[0], bh[1]);                            \
            mma16816(acc[2 * p + 1], ah, bh[2], bh[3]);                            \
            mma16816(acc[2 * p + 1], ah, bl[2], bl[3]);                            \
            mma16816(acc[2 * p + 1], al, bh[2], bh[3]);                            \
        }                                                                          \
    }

#define STAGE_ACC16(Cs)                                                            \
    {                                                                              \
        const int rf = m0w + (lane >> 2);                                          \
        const int cf = (lane & 3) * 2;                                             \
        _Pragma("unroll")                                                          \
        for (int half = 0; half < 2; half++) {                                     \
            int rr = rf + half * 8;                                                \
            _Pragma("unroll")                                                      \
            for (int nt = 0; nt < 10; nt++) {                                      \
                float* pp = &(Cs)[rr * 84 + cf + nt * 8];                          \
                pp[0] = acc[nt][half * 2 + 0];                                     \
                pp[1] = acc[nt][half * 2 + 1];                                     \
            }                                                                      \
        }                                                                          \
    }

// ---------------- H0 kernel, N-split ----------------
#define WS3 24
#define O3_WHI 0
#define O3_WLO 3840
#define O3_AHI 7680
#define O3_ALO 13824
#define H0_SMEM (128 * 84 * 4)   // 43008 B

__global__ __launch_bounds__(256, 3) void k_h0(
    const unsigned short* __restrict__ EAhi, const unsigned short* __restrict__ EAlo,
    const unsigned short* __restrict__ Whi, const unsigned short* __restrict__ Wlo,
    const float* __restrict__ P,
    const int* __restrict__ srcIdx, const int* __restrict__ dstIdx,
    unsigned short* __restrict__ OutHi, unsigned short* __restrict__ OutLo,
    float* __restrict__ Sred)
{
    extern __shared__ char smem[];
    const uint32_t sbase = cvta_s(smem);
    const int tid = threadIdx.x;
    const int lane = tid & 31, wid = tid >> 5;
    const int m0w = wid * 16;
    const int colhalf = blockIdx.x & 1;
    const int row0 = (blockIdx.x >> 1) * 128;
    const int coff = colhalf * 80;

    // prefetch gathered P rows (this col half) into L2
    for (int idx = tid; idx < 384; idx += 256) {
        int r = idx / 3, s = idx - r * 3;
        int row = row0 + r;
        if (row < NE)
            prefetchL2(P + (size_t)srcIdx[row] * DIM + coff + s * 32);
    }

    // W slice: 80 output rows x 16 k (cols 160..175 of stride-176), via cp.async
    if (tid < 160) {
        int h = tid >> 1, s = tid & 1;
        uint32_t d = (uint32_t)(h * (WS3 * 2) + s * 16);
        const int gi = (coff + h) * 176 + 160 + s * 8;
        cp16(sbase + O3_WHI + d, Whi + gi);
        cp16(sbase + O3_WLO + d, Wlo + gi);
    }
    // A: 128 rows x 32B (pre-split ea)
    {
        int r = tid >> 1, s = tid & 1;
        int row = row0 + r;
        uint32_t d = (uint32_t)(r * (WS3 * 2) + s * 16);
        if (row < NE) {
            const size_t gi = (size_t)row * 16 + s * 8;
            cp16(sbase + O3_AHI + d, EAhi + gi);
            cp16(sbase + O3_ALO + d, EAlo + gi);
        } else {
            uint4 z = make_uint4(0, 0, 0, 0);
            *(uint4*)(smem + O3_AHI + d) = z;
            *(uint4*)(smem + O3_ALO + d) = z;
        }
    }
    asm volatile("cp.async.commit_group;");

    float acc[10][4];
#pragma unroll
    for (int t = 0; t < 10; t++)
#pragma unroll
        for (int j = 0; j < 4; j++) acc[t][j] = 0.f;

    asm volatile("cp.async.wait_group 0;");
    __syncthreads();

    const int arow = (lane & 7) + ((lane >> 3) & 1) * 8;
    const int acol = (lane >> 4) * 8;
    const uint32_t aAhi = sbase + O3_AHI + (uint32_t)((m0w + arow) * WS3 + acol) * 2;
    const uint32_t aAlo = sbase + O3_ALO + (uint32_t)((m0w + arow) * WS3 + acol) * 2;
    const int brow = (lane & 7) + ((lane >> 4) << 3);
    const int bcol = ((lane >> 3) & 1) * 8;
    const uint32_t bWhi = sbase + O3_WHI + (uint32_t)(brow * WS3 + bcol) * 2;
    const uint32_t bWlo = sbase + O3_WLO + (uint32_t)(brow * WS3 + bcol) * 2;

    MMA16_BODY(aAhi, aAlo, bWhi, bWlo, 1, WS3)

    __syncthreads();
    float* Cs = (float*)smem;
    STAGE_ACC16(Cs)
    __syncthreads();

    for (int idx = tid; idx < 128 * 10; idx += 256) {
        int r = idx / 10, u = idx - r * 10;
        int row = row0 + r;
        if (row >= NE) continue;
        float4 v0 = *reinterpret_cast<float4*>(&Cs[r * 84 + u * 8]);
        float4 v1 = *reinterpret_cast<float4*>(&Cs[r * 84 + u * 8 + 4]);
        const float* gp = P + (size_t)srcIdx[row] * DIM + coff + u * 8;
        float4 g0 = __ldg((const float4*)gp);
        float4 g1 = __ldg((const float4*)(gp + 4));
        v0.x = fmaxf(v0.x + g0.x, 0.f); v0.y = fmaxf(v0.y + g0.y, 0.f);
        v0.z = fmaxf(v0.z + g0.z, 0.f); v0.w = fmaxf(v0.w + g0.w, 0.f);
        v1.x = fmaxf(v1.x + g1.x, 0.f); v1.y = fmaxf(v1.y + g1.y, 0.f);
        v1.z = fmaxf(v1.z + g1.z, 0.f); v1.w = fmaxf(v1.w + g1.w, 0.f);
        uint4 H, L;
        split2(v0.x, v0.y, H.x, L.x);
        split2(v0.z, v0.w, H.y, L.y);
        split2(v1.x, v1.y, H.z, L.z);
        split2(v1.z, v1.w, H.w, L.w);
        *(uint4*)&OutHi[(size_t)row * DIM + coff + u * 8] = H;
        *(uint4*)&OutLo[(size_t)row * DIM + coff + u * 8] = L;
        float* p = Sred + (size_t)dstIdx[row] * DIM + coff + u * 8;
        redv4(p, v0);
        redv4(p + 4, v1);
    }
}

// ---------------- edge kernel, N-split + pipelined ----------------
#define WS2 40
#define SSTG 33280
#define S_WHI 0
#define S_WLO 6400
#define S_AHI 12800
#define S_ALO 23040
#define EDGE_SMEM (2 * SSTG)   // 66560 B

__global__ __launch_bounds__(256, 3) void k_edge(
    const unsigned short* __restrict__ Ahi, const unsigned short* __restrict__ Alo,
    const unsigned short* __restrict__ Whi, const unsigned short* __restrict__ Wlo,
    const unsigned short* __restrict__ H0hi, const unsigned short* __restrict__ H0lo,
    const float* __restrict__ T,
    const float* __restrict__ bias,
    const int* __restrict__ srcIdx, const int* __restrict__ dstIdx,
    unsigned short* __restrict__ OutHi, unsigned short* __restrict__ OutLo,
    float* __restrict__ Sred)
{
    extern __shared__ char smem[];
    const uint32_t sbase = cvta_s(smem);

    const int tid = threadIdx.x;
    const int lane = tid & 31, wid = tid >> 5;
    const int m0w = wid * 16;
    const int colhalf = blockIdx.x & 1;
    const int row0 = (blockIdx.x >> 1) * 128;
    const int coff = colhalf * 80;

    // prefetch gathered T rows (this col half) into L2
    for (int idx = tid; idx < 384; idx += 256) {
        int r = idx / 3, s = idx - r * 3;
        int row = row0 + r;
        if (row < NE)
            prefetchL2(T + (size_t)srcIdx[row] * DIM + coff + s * 32);
    }

    const int arow = (lane & 7) + ((lane >> 3) & 1) * 8;
    const int acol = (lane >> 4) * 8;
    const uint32_t aoff = S_AHI + (uint32_t)((m0w + arow) * WS2 + acol) * 2;
    const int brow = (lane & 7) + ((lane >> 4) << 3);
    const int bcol = ((lane >> 3) & 1) * 8;
    const uint32_t boff = S_WHI + (uint32_t)(brow * WS2 + bcol) * 2;

    float acc[10][4];
#pragma unroll
    for (int t = 0; t < 10; t++)
#pragma unroll
        for (int j = 0; j < 4; j++) acc[t][j] = 0.f;

    auto load_chunk = [&](int c) {
        const uint32_t sb = sbase + (uint32_t)(c & 1) * SSTG;
        const int k0 = c * 32;
        // W: 80 rows x 4 segs (hi+lo)
        for (int idx = tid; idx < 320; idx += 256) {
            int h = idx >> 2, s = idx & 3;
            uint32_t d = sb + (uint32_t)((h * WS2 + s * 8) * 2);
            const int gi = (coff + h) * 160 + k0 + s * 8;
            cp16(d + S_WHI, Whi + gi);
            cp16(d + S_WLO, Wlo + gi);
        }
        // A: 128 rows x 4 segs (hi+lo)
        for (int idx = tid; idx < 512; idx += 256) {
            int r = idx >> 2, s = idx & 3;
            int row = row0 + r;
            uint32_t d = sb + S_AHI + (uint32_t)((r * WS2 + s * 8) * 2);
            if (row < NE) {
                const size_t gi = (size_t)row * DIM + k0 + s * 8;
                cp16(d, Ahi + gi);
                cp16(d + (S_ALO - S_AHI), Alo + gi);
            } else {
                size_t off = (size_t)(c & 1) * SSTG + S_AHI + (r * WS2 + s * 8) * 2;
                uint4 z = make_uint4(0, 0, 0, 0);
                *(uint4*)(smem + off) = z;
                *(uint4*)(smem + off + (S_ALO - S_AHI)) = z;
            }
        }
        asm volatile("cp.async.commit_group;");
    };

    load_chunk(0);
    load_chunk(1);

#pragma unroll
    for (int c = 0; c < 5; c++) {
        if (c < 4) asm volatile("cp.async.wait_group 1;");
        else       asm volatile("cp.async.wait_group 0;");
        __syncthreads();
        const uint32_t sb = (uint32_t)(c & 1) * SSTG;
        const uint32_t aAhi = sbase + sb + aoff;
        const uint32_t aAlo = aAhi + (S_ALO - S_AHI);
        const uint32_t bWhi = sbase + sb + boff;
        const uint32_t bWlo = bWhi + (S_WLO - S_WHI);
        MMA16_BODY(aAhi, aAlo, bWhi, bWlo, 2, WS2)
        if (c < 3) {
            __syncthreads();
            load_chunk(c + 2);
        }
    }

    __syncthreads();
    float* Cs = (float*)smem;
    STAGE_ACC16(Cs)
    __syncthreads();

    for (int idx = tid; idx < 128 * 10; idx += 256) {
        int r = idx / 10, u = idx - r * 10;
        int row = row0 + r;
        if (row >= NE) continue;
        float4 g0 = *reinterpret_cast<float4*>(&Cs[(r ^ 1) * 84 + u * 8]);
        float4 g1 = *reinterpret_cast<float4*>(&Cs[(r ^ 1) * 84 + u * 8 + 4]);
        uint4 hh = *(const uint4*)&H0hi[(size_t)row * DIM + coff + u * 8];
        uint4 hl = *(const uint4*)&H0lo[(size_t)row * DIM + coff + u * 8];
        float2 ha = recon2(hh.x, hl.x), hb = recon2(hh.y, hl.y);
        float2 hc = recon2(hh.z, hl.z), hd = recon2(hh.w, hl.w);
        const float* tp = T + (size_t)srcIdx[row] * DIM + coff + u * 8;
        float4 t0 = __ldg((const float4*)tp);
        float4 t1 = __ldg((const float4*)(tp + 4));
        float4 b0 = __ldg((const float4*)(bias + coff + u * 8));
        float4 b1 = __ldg((const float4*)(bias + coff + u * 8 + 4));
        float4 v0, v1;
        v0.x = fmaxf(ha.x + t0.x - g0.x + b0.x, 0.f);
        v0.y = fmaxf(ha.y + t0.y - g0.y + b0.y, 0.f);
        v0.z = fmaxf(hb.x + t0.z - g0.z + b0.z, 0.f);
        v0.w = fmaxf(hb.y + t0.w - g0.w + b0.w, 0.f);
        v1.x = fmaxf(hc.x + t1.x - g1.x + b1.x, 0.f);
        v1.y = fmaxf(hc.y + t1.y - g1.y + b1.y, 0.f);
        v1.z = fmaxf(hd.x + t1.z - g1.z + b1.z, 0.f);
        v1.w = fmaxf(hd.y + t1.w - g1.w + b1.w, 0.f);
        if (OutHi) {
            uint4 H, L;
            split2(v0.x, v0.y, H.x, L.x);
            split2(v0.z, v0.w, H.y, L.y);
            split2(v1.x, v1.y, H.z, L.z);
            split2(v1.z, v1.w, H.w, L.w);
            *(uint4*)&OutHi[(size_t)row * DIM + coff + u * 8] = H;
            *(uint4*)&OutLo[(size_t)row * DIM + coff + u * 8] = L;
        }
        float* p = Sred + (size_t)dstIdx[row] * DIM + coff + u * 8;
        redv4(p, v0);
        redv4(p + 4, v1);
    }
}

// ---------------- where(rowsum==0, x, M) ----------------
__global__ void k_where(float* __restrict__ M, const float* __restrict__ x)
{
    int gt = blockIdx.x * blockDim.x + threadIdx.x;
    int n = gt >> 5;
    int lane = gt & 31;
    if (n >= NN) return;
    float s = 0.f;
#pragma unroll
    for (int j = 0; j < 5; j++) s += M[n * DIM + lane + j * 32];
#pragma unroll
    for (int o = 16; o; o >>= 1) s += __shfl_xor_sync(0xffffffffu, s, o);
    if (s == 0.f) {
#pragma unroll
        for (int j = 0; j < 5; j++)
            M[n * DIM + lane + j * 32] = x[n * DIM + lane + j * 32];
    }
}

// ---------------- launch ----------------
extern "C" void kernel_launch(void* const* d_in, const int* in_sizes, int n_in,
                              void* d_out, int out_size)
{
    const float* x    = (const float*)d_in[0];
    const float* ea   = (const float*)d_in[1];
    const void*  eidx = d_in[2];
    const float* Wi_w = (const float*)d_in[4];
    const float* Wi_b = (const float*)d_in[5];
    const float* Wh_w = (const float*)d_in[6];
    const float* Wh_b = (const float*)d_in[7];
    const float* Wo_w = (const float*)d_in[8];
    const float* Wo_b = (const float*)d_in[9];
    float* out = (float*)d_out;

    void *pP, *pHhi, *pHlo, *pGhi, *pGlo, *pEAhi, *pEAlo, *pS0, *pS1, *pM1, *pT, *pSrc, *pDst;
    void *pWih, *pWil, *pWhh, *pWhl, *pWoh, *pWol;
    cudaGetSymbolAddress(&pP,    g_P);
    cudaGetSymbolAddress(&pHhi,  g_Hhi);
    cudaGetSymbolAddress(&pHlo,  g_Hlo);
    cudaGetSymbolAddress(&pGhi,  g_Ghi);
    cudaGetSymbolAddress(&pGlo,  g_Glo);
    cudaGetSymbolAddress(&pEAhi, g_EAhi);
    cudaGetSymbolAddress(&pEAlo, g_EAlo);
    cudaGetSymbolAddress(&pS0,   g_S0);
    cudaGetSymbolAddress(&pS1,   g_S1);
    cudaGetSymbolAddress(&pM1,   g_M1);
    cudaGetSymbolAddress(&pT,    g_T);
    cudaGetSymbolAddress(&pSrc,  g_src);
    cudaGetSymbolAddress(&pDst,  g_dst);
    cudaGetSymbolAddress(&pWih,  g_Wih);
    cudaGetSymbolAddress(&pWil,  g_Wil);
    cudaGetSymbolAddress(&pWhh,  g_Whh);
    cudaGetSymbolAddress(&pWhl,  g_Whl);
    cudaGetSymbolAddress(&pWoh,  g_Woh);
    cudaGetSymbolAddress(&pWol,  g_Wol);

    cudaFuncSetAttribute(k_mma,  cudaFuncAttributeMaxDynamicSharedMemorySize, MMA_SMEM);
    cudaFuncSetAttribute(k_h0,   cudaFuncAttributeMaxDynamicSharedMemorySize, H0_SMEM);
    cudaFuncSetAttribute(k_edge, cudaFuncAttributeMaxDynamicSharedMemorySize, EDGE_SMEM);

    const int gridE2 = 2 * ((NE + 127) / 128);   // 7814 (row tile x col half)
    const int gridN = (NN + 127) / 128;
    const int gridW = (NN * 32) / 256;

    // 1) prep: indices + zero + ea pre-split
    k_prep<<<2048, 256>>>(eidx, ea, (float*)pS0, (float*)pS1, (float*)pM1);

    // 2) weight split
    const int nsplit = 160 * 176 + 160 * 160 + 160 * 320;
    k_wsplit_all<<<(nsplit + 255) / 256, 256>>>(Wi_w, Wh_w, Wo_w);

    // 3) P = x @ Wi_x^T + Wi_b
    k_mma<<<gridN, 256, MMA_SMEM>>>(x, DIM, DIM, 0, nullptr, 0, 0, 0, 1, NN,
                                    (const unsigned short*)pWih, (const unsigned short*)pWil, 176,
                                    Wi_b, 0, (float*)pP);

    // 4) H0 pass (N-split): split store + S0 red
    k_h0<<<gridE2, 256, H0_SMEM>>>((const unsigned short*)pEAhi, (const unsigned short*)pEAlo,
                                   (const unsigned short*)pWih, (const unsigned short*)pWil,
                                   (const float*)pP, (const int*)pSrc, (const int*)pDst,
                                   (unsigned short*)pHhi, (unsigned short*)pHlo,
                                   (float*)pS0);

    // 5) T = S0 @ Wh^T
    k_mma<<<gridN, 256, MMA_SMEM>>>((const float*)pS0, DIM, DIM, 0, nullptr, 0, 0, 0, 1, NN,
                                    (const unsigned short*)pWhh, (const unsigned short*)pWhl, DIM,
                                    nullptr, 0, (float*)pT);

    // 6) iter1
    k_edge<<<gridE2, 256, EDGE_SMEM>>>((const unsigned short*)pHhi, (const unsigned short*)pHlo,
                                       (const unsigned short*)pWhh, (const unsigned short*)pWhl,
                                       (const unsigned short*)pHhi, (const unsigned short*)pHlo,
                                       (const float*)pT, Wh_b,
                                       (const int*)pSrc, (const int*)pDst,
                                       (unsigned short*)pGhi, (unsigned short*)pGlo,
                                       (float*)pS1);

    // 7) T = S1 @ Wh^T
    k_mma<<<gridN, 256, MMA_SMEM>>>((const float*)pS1, DIM, DIM, 0, nullptr, 0, 0, 0, 1, NN,
                                    (const unsigned short*)pWhh, (const unsigned short*)pWhl, DIM,
                                    nullptr, 0, (float*)pT);

    // 8) iter2
    k_edge<<<gridE2, 256, EDGE_SMEM>>>((const unsigned short*)pGhi, (const unsigned short*)pGlo,
                                       (const unsigned short*)pWhh, (const unsigned short*)pWhl,
                                       (const unsigned short*)pHhi, (const unsigned short*)pHlo,
                                       (const float*)pT, Wh_b,
                                       (const int*)pSrc, (const int*)pDst,
                                       nullptr, nullptr,
                                       (float*)pM1);

    // 9) where
    k_where<<<gridW, 256>>>((float*)pM1, x);

    // 10) out = relu([x ; M1] @ Wo^T + Wo_b)
    k_mma<<<gridN, 256, MMA_SMEM>>>(x, DIM, DIM, 0, (const float*)pM1, DIM, DIM, DIM, 2, NN,
                                    (const unsigned short*)pWoh, (const unsigned short*)pWol, 2 * DIM,
                                    Wo_b, 1, out);
}

// round 11
// speedup vs baseline: 1.0735x; 1.0735x over previous
#include <cuda_runtime.h>
#include <cstdint>

#define NN 50000
#define NE 500000
#define DIM 160
#define BOND 14
#define WS 88   // k_mma padded k-stride (bf16); 176B rows, conflict-free ldsm

// ---------------- scratch ----------------
__device__ int   g_src[NE];
__device__ int   g_dst[NE];
__device__ float g_P [NN * DIM];
__device__ unsigned short g_Hhi[NE * DIM], g_Hlo[NE * DIM];   // H0 split-bf16
__device__ unsigned short g_Ghi[NE * DIM], g_Glo[NE * DIM];   // H1 split-bf16
__device__ unsigned short g_EAhi[NE * 16], g_EAlo[NE * 16];   // padded split ea [NE,16]
__device__ float g_S0[NN * DIM];
__device__ float g_S1[NN * DIM];
__device__ float g_M1[NN * DIM];
__device__ float g_T [NN * DIM];
__device__ unsigned short g_Wih[160 * 176], g_Wil[160 * 176];
__device__ unsigned short g_Whh[160 * 160], g_Whl[160 * 160];
__device__ unsigned short g_Woh[160 * 320], g_Wol[160 * 320];

// ---------------- helpers ----------------
__device__ __forceinline__ uint32_t cvta_s(const void* p) {
    uint32_t r;
    asm("{ .reg .u64 t; cvta.to.shared.u64 t, %1; cvt.u32.u64 %0, t; }" : "=r"(r) : "l"(p));
    return r;
}
__device__ __forceinline__ void ldsm4(uint32_t (&r)[4], uint32_t addr) {
    asm volatile("ldmatrix.sync.aligned.m8n8.x4.shared.b16 {%0,%1,%2,%3}, [%4];"
                 : "=r"(r[0]), "=r"(r[1]), "=r"(r[2]), "=r"(r[3]) : "r"(addr));
}
__device__ __forceinline__ void mma16816(float* c, const uint32_t (&a)[4],
                                         uint32_t b0, uint32_t b1) {
    asm volatile("mma.sync.aligned.m16n8k16.row.col.f32.bf16.bf16.f32 "
                 "{%0,%1,%2,%3},{%4,%5,%6,%7},{%8,%9},{%0,%1,%2,%3};"
                 : "+f"(c[0]), "+f"(c[1]), "+f"(c[2]), "+f"(c[3])
                 : "r"(a[0]), "r"(a[1]), "r"(a[2]), "r"(a[3]), "r"(b0), "r"(b1));
}
__device__ __forceinline__ void split2(float x, float y, uint32_t& hi2, uint32_t& lo2) {
    uint32_t ux = __float_as_uint(x), uy = __float_as_uint(y);
    hi2 = __byte_perm(ux, uy, 0x7632);
    float lx = x - __uint_as_float(ux & 0xffff0000u);
    float ly = y - __uint_as_float(uy & 0xffff0000u);
    asm("cvt.rn.bf16x2.f32 %0, %1, %2;" : "=r"(lo2) : "f"(ly), "f"(lx));
}
__device__ __forceinline__ float2 recon2(uint32_t hi2, uint32_t lo2) {
    float2 r;
    r.x = __uint_as_float(hi2 << 16) + __uint_as_float(lo2 << 16);
    r.y = __uint_as_float(hi2 & 0xffff0000u) + __uint_as_float(lo2 & 0xffff0000u);
    return r;
}
__device__ __forceinline__ void cp16(uint32_t dst, const void* src) {
    asm volatile("cp.async.cg.shared.global [%0], [%1], 16;" :: "r"(dst), "l"(src));
}
__device__ __forceinline__ void redv4(float* p, float4 v) {
    asm volatile("red.global.add.v4.f32 [%0], {%1,%2,%3,%4};"
                 :: "l"(p), "f"(v.x), "f"(v.y), "f"(v.z), "f"(v.w) : "memory");
}
__device__ __forceinline__ void prefetchL2(const void* p) {
    asm volatile("prefetch.global.L2 [%0];" :: "l"(p));
}

// ---------------- prep: indices + zero + ea pre-split ----------------
__global__ void k_prep(const void* ei, const float* __restrict__ ea,
                       float* S0, float* S1, float* M1) {
    __shared__ int s64;
    if (threadIdx.x < 32) {
        const unsigned long long* p = (const unsigned long long*)ei;
        int bad = 0;
        for (int j = threadIdx.x; j < 1024; j += 32)
            if (p[j] >= (unsigned long long)NN) bad = 1;
        unsigned m = __ballot_sync(0xffffffffu, bad);
        if (threadIdx.x == 0) s64 = (m == 0u);
    }
    __syncthreads();
    const int is64 = s64;
    const int gstride = gridDim.x * blockDim.x;
    int g = blockIdx.x * blockDim.x + threadIdx.x;
    for (int i = g; i < NE; i += gstride) {
        if (is64) {
            const long long* p = (const long long*)ei;
            g_src[i] = (int)p[i];
            g_dst[i] = (int)p[NE + i];
        } else {
            const int* p = (const int*)ei;
            g_src[i] = p[i];
            g_dst[i] = p[NE + i];
        }
    }
    const int nz = NN * DIM / 4;
    float4 z = make_float4(0.f, 0.f, 0.f, 0.f);
    for (int i = g; i < nz; i += gstride) {
        reinterpret_cast<float4*>(S0)[i] = z;
        reinterpret_cast<float4*>(S1)[i] = z;
        reinterpret_cast<float4*>(M1)[i] = z;
    }
    // ea split: [NE,14] fp32 -> [NE,16] split-bf16 (pairs)
    uint32_t* eh = (uint32_t*)g_EAhi;
    uint32_t* el = (uint32_t*)g_EAlo;
    for (int i = g; i < NE * 8; i += gstride) {
        int e = i >> 3, c2 = (i & 7) << 1;
        float2 f = (c2 < BOND) ? *(const float2*)(ea + (size_t)e * BOND + c2)
                               : make_float2(0.f, 0.f);
        uint32_t h2, l2;
        split2(f.x, f.y, h2, l2);
        eh[i] = h2;
        el[i] = l2;
    }
}

// ---------------- weight split ----------------
__global__ void k_wsplit_all(const float* __restrict__ wi, const float* __restrict__ wh,
                             const float* __restrict__ wo) {
    int i = blockIdx.x * blockDim.x + threadIdx.x;
    const int nWi = 160 * 176, nWh = 160 * 160, nWo = 160 * 320;
    float f;
    unsigned short* hi;
    unsigned short* lo;
    int oi;
    if (i < nWi) {
        int h = i / 176, c = i - h * 176;
        f = (c < 174) ? wi[h * 174 + c] : 0.f;
        hi = g_Wih; lo = g_Wil; oi = i;
    } else if (i < nWi + nWh) {
        oi = i - nWi;
        f = wh[oi];
        hi = g_Whh; lo = g_Whl;
    } else if (i < nWi + nWh + nWo) {
        oi = i - nWi - nWh;
        f = wo[oi];
        hi = g_Woh; lo = g_Wol;
    } else return;
    uint32_t u = __float_as_uint(f);
    hi[oi] = (unsigned short)(u >> 16);
    float lf = f - __uint_as_float(u & 0xffff0000u);
    unsigned short ls;
    asm("cvt.rn.bf16.f32 %0, %1;" : "=h"(ls) : "f"(lf));
    lo[oi] = ls;
}

// ---------------- k_mma smem layout ----------------
#define OFF_WHI 0
#define OFF_WLO (160 * WS * 2)
#define OFF_AHI (2 * 160 * WS * 2)
#define OFF_ALO (2 * 160 * WS * 2 + 128 * WS * 2)
#define MMA_SMEM (2 * 160 * WS * 2 + 2 * 128 * WS * 2)   // 101376 B

#define MMA_BODY(aAhi, aAlo, bWhi, bWlo, ksteps, ws)                               \
    for (int ks = 0; ks < (ksteps); ks++) {                                        \
        const uint32_t ko = (uint32_t)ks * 32;                                     \
        uint32_t ah0[4], ah1[4], al0[4], al1[4];                                   \
        ldsm4(ah0, (aAhi) + ko);                                                   \
        ldsm4(ah1, (aAhi) + ko + 16 * (ws) * 2);                                   \
        ldsm4(al0, (aAlo) + ko);                                                   \
        ldsm4(al1, (aAlo) + ko + 16 * (ws) * 2);                                   \
        _Pragma("unroll")                                                          \
        for (int p = 0; p < 5; p++) {                                              \
            const uint32_t bo = ko + (uint32_t)p * (16 * (ws) * 2);                \
            uint32_t bh[4], bl[4];                                                 \
            ldsm4(bh, (bWhi) + bo);                                                \
            ldsm4(bl, (bWlo) + bo);                                                \
            mma16816(acc[2 * p],      ah0, bh[0], bh[1]);                          \
            mma16816(acc[2 * p],      ah0, bl[0], bl[1]);                          \
            mma16816(acc[2 * p],      al0, bh[0], bh[1]);                          \
            mma16816(acc[2 * p + 1],  ah0, bh[2], bh[3]);                          \
            mma16816(acc[2 * p + 1],  ah0, bl[2], bl[3]);                          \
            mma16816(acc[2 * p + 1],  al0, bh[2], bh[3]);                          \
            mma16816(acc[10 + 2 * p],     ah1, bh[0], bh[1]);                      \
            mma16816(acc[10 + 2 * p],     ah1, bl[0], bl[1]);                      \
            mma16816(acc[10 + 2 * p],     al1, bh[0], bh[1]);                      \
            mma16816(acc[10 + 2 * p + 1], ah1, bh[2], bh[3]);                      \
            mma16816(acc[10 + 2 * p + 1], ah1, bl[2], bl[3]);                      \
            mma16816(acc[10 + 2 * p + 1], al1, bh[2], bh[3]);                      \
        }                                                                          \
    }

#define STAGE_ACC(Cs)                                                              \
    {                                                                              \
        const int rf = m0w + (lane >> 2);                                          \
        const int cf = n0w + (lane & 3) * 2;                                       \
        _Pragma("unroll")                                                          \
        for (int mt = 0; mt < 2; mt++)                                             \
            _Pragma("unroll")                                                      \
            for (int half = 0; half < 2; half++) {                                 \
                int rr = rf + mt * 16 + half * 8;                                  \
                _Pragma("unroll")                                                  \
                for (int nt = 0; nt < 10; nt++) {                                  \
                    float* pp = &(Cs)[rr * 164 + cf + nt * 8];                     \
                    pp[0] = acc[mt * 10 + nt][half * 2 + 0];                       \
                    pp[1] = acc[mt * 10 + nt][half * 2 + 1];                       \
                }                                                                  \
            }                                                                      \
    }

// ---------------- generic GEMM (P, T, out) ----------------
__global__ __launch_bounds__(256, 2) void k_mma(
    const float* __restrict__ A0, int lda0, int klen0, int wk0,
    const float* __restrict__ A1, int lda1, int klen1, int wk1,
    int nph, int M,
    const unsigned short* __restrict__ Whi, const unsigned short* __restrict__ Wlo, int ldw,
    const float* __restrict__ bias, int dorelu,
    float* __restrict__ Cout)
{
    extern __shared__ char smem[];
    unsigned short* Whi_s = (unsigned short*)(smem + OFF_WHI);
    unsigned short* Wlo_s = (unsigned short*)(smem + OFF_WLO);
    unsigned short* Ahi_s = (unsigned short*)(smem + OFF_AHI);
    unsigned short* Alo_s = (unsigned short*)(smem + OFF_ALO);
    const uint32_t sbase = cvta_s(smem);

    const int tid = threadIdx.x;
    const int lane = tid & 31, wid = tid >> 5;
    const int warp_m = wid & 3, warp_n = wid >> 2;
    const int m0w = warp_m * 32, n0w = warp_n * 80;
    const int row0 = blockIdx.x * 128;

    const int arow = (lane & 7) + ((lane >> 3) & 1) * 8;
    const int acol = (lane >> 4) * 8;
    const uint32_t aAhi = sbase + OFF_AHI + (uint32_t)((m0w + arow) * WS + acol) * 2;
    const uint32_t aAlo = sbase + OFF_ALO + (uint32_t)((m0w + arow) * WS + acol) * 2;
    const int brow = (lane & 7) + ((lane >> 4) << 3);
    const int bcol = ((lane >> 3) & 1) * 8;
    const uint32_t bWhi = sbase + OFF_WHI + (uint32_t)((n0w + brow) * WS + bcol) * 2;
    const uint32_t bWlo = sbase + OFF_WLO + (uint32_t)((n0w + brow) * WS + bcol) * 2;

    float acc[20][4];
#pragma unroll
    for (int t = 0; t < 20; t++)
#pragma unroll
        for (int j = 0; j < 4; j++) acc[t][j] = 0.f;

    for (int ph = 0; ph < nph; ph++) {
        const float* A = (ph == 0) ? A0 : A1;
        const int lda  = (ph == 0) ? lda0 : lda1;
        const int klen = (ph == 0) ? klen0 : klen1;
        const int wk   = (ph == 0) ? wk0 : wk1;
        const int nch = (klen + 79) / 80;

        for (int c = 0; c < nch; c++) {
            const int k0g = c * 80;
            const int kc = min(80, klen - k0g);
            const bool cpW = (kc == 80) && ((ldw & 7) == 0) && (((wk + k0g) & 7) == 0);
            __syncthreads();

            if (cpW) {
                for (int idx = tid; idx < 160 * 10; idx += 256) {
                    int h = idx / 10, s = idx - h * 10;
                    uint32_t d = (uint32_t)((h * WS + s * 8) * 2);
                    const int gi = h * ldw + wk + k0g + s * 8;
                    cp16(sbase + OFF_WHI + d, Whi + gi);
                    cp16(sbase + OFF_WLO + d, Wlo + gi);
                }
                asm volatile("cp.async.commit_group;");
            } else {
                const int kpad = (kc + 15) & ~15;
                for (int idx = tid; idx < 160 * kpad; idx += 256) {
                    int h = idx / kpad, kk = idx - h * kpad;
                    unsigned short vh = 0, vl = 0;
                    if (kk < kc) {
                        int gi = h * ldw + wk + k0g + kk;
                        vh = Whi[gi]; vl = Wlo[gi];
                    }
                    Whi_s[h * WS + kk] = vh;
                    Wlo_s[h * WS + kk] = vl;
                }
            }

            if (kc == 80 && (lda & 3) == 0) {
                for (int idx = tid; idx < 128 * 20; idx += 256) {
                    int r = idx / 20, q = idx - r * 20;
                    int row = row0 + r;
                    float4 v = make_float4(0.f, 0.f, 0.f, 0.f);
                    if (row < M)
                        v = *reinterpret_cast<const float4*>(A + (size_t)row * lda + k0g + q * 4);
                    uint32_t h2a, l2a, h2b, l2b;
                    split2(v.x, v.y, h2a, l2a);
                    split2(v.z, v.w, h2b, l2b);
                    *(uint2*)&Ahi_s[r * WS + q * 4] = make_uint2(h2a, h2b);
                    *(uint2*)&Alo_s[r * WS + q * 4] = make_uint2(l2a, l2b);
                }
            } else {
                const int kpad = (kc + 15) & ~15;
                for (int idx = tid; idx < 128 * kpad; idx += 256) {
                    int r = idx / kpad, kk = idx - r * kpad;
                    int row = row0 + r;
                    float f = 0.f;
                    if (row < M && kk < kc) f = A[(size_t)row * lda + k0g + kk];
                    uint32_t u = __float_as_uint(f);
                    Ahi_s[r * WS + kk] = (unsigned short)(u >> 16);
                    float lf = f - __uint_as_float(u & 0xffff0000u);
                    unsigned short ls;
                    asm("cvt.rn.bf16.f32 %0, %1;" : "=h"(ls) : "f"(lf));
                    Alo_s[r * WS + kk] = ls;
                }
            }

            if (cpW) asm volatile("cp.async.wait_group 0;");
            __syncthreads();

            const int ksteps = ((kc + 15) & ~15) >> 4;
            MMA_BODY(aAhi, aAlo, bWhi, bWlo, ksteps, WS)
        }
    }

    __syncthreads();
    float* Cs = (float*)smem;
    STAGE_ACC(Cs)
    __syncthreads();

    for (int idx = tid; idx < 128 * 20; idx += 256) {
        int r = idx / 20, u = idx - r * 20;
        int row = row0 + r;
        if (row >= M) continue;
        float4 v0 = *reinterpret_cast<float4*>(&Cs[r * 164 + u * 8]);
        float4 v1 = *reinterpret_cast<float4*>(&Cs[r * 164 + u * 8 + 4]);
        if (bias) {
            float4 b0 = __ldg((const float4*)(bias + u * 8));
            float4 b1 = __ldg((const float4*)(bias + u * 8 + 4));
            v0.x += b0.x; v0.y += b0.y; v0.z += b0.z; v0.w += b0.w;
            v1.x += b1.x; v1.y += b1.y; v1.z += b1.z; v1.w += b1.w;
        }
        if (dorelu) {
            v0.x = fmaxf(v0.x, 0.f); v0.y = fmaxf(v0.y, 0.f);
            v0.z = fmaxf(v0.z, 0.f); v0.w = fmaxf(v0.w, 0.f);
            v1.x = fmaxf(v1.x, 0.f); v1.y = fmaxf(v1.y, 0.f);
            v1.z = fmaxf(v1.z, 0.f); v1.w = fmaxf(v1.w, 0.f);
        }
        float4* cp = (float4*)(Cout + (size_t)row * DIM + u * 8);
        cp[0] = v0; cp[1] = v1;
    }
}

// ---------------- dedicated H0 kernel (R9 config) ----------------
#define WS3 24
#define O3_WHI 0
#define O3_WLO 7680
#define O3_AHI 15360
#define O3_ALO 21504
#define H0_SMEM (128 * 164 * 4)   // 83968 B; 2 CTAs/SM

__global__ __launch_bounds__(256, 2) void k_h0(
    const unsigned short* __restrict__ EAhi, const unsigned short* __restrict__ EAlo,
    const unsigned short* __restrict__ Whi, const unsigned short* __restrict__ Wlo,
    const float* __restrict__ P,
    const int* __restrict__ srcIdx, const int* __restrict__ dstIdx,
    unsigned short* __restrict__ OutHi, unsigned short* __restrict__ OutLo,
    float* __restrict__ Sred)
{
    extern __shared__ char smem[];
    const uint32_t sbase = cvta_s(smem);
    const int tid = threadIdx.x;
    const int lane = tid & 31, wid = tid >> 5;
    const int warp_m = wid & 3, warp_n = wid >> 2;
    const int m0w = warp_m * 32, n0w = warp_n * 80;
    const int row0 = blockIdx.x * 128;

    for (int idx = tid; idx < 640; idx += 256) {
        int r = idx / 5, s = idx - r * 5;
        int row = row0 + r;
        if (row < NE)
            prefetchL2(P + (size_t)srcIdx[row] * DIM + s * 32);
    }

    for (int idx = tid; idx < 320; idx += 256) {
        int h = idx >> 1, s = idx & 1;
        uint32_t d = (uint32_t)(h * (WS3 * 2) + s * 16);
        const int gi = h * 176 + 160 + s * 8;
        cp16(sbase + O3_WHI + d, Whi + gi);
        cp16(sbase + O3_WLO + d, Wlo + gi);
    }
    {
        int idx = tid;
        if (idx < 256) {
            int r = idx >> 1, s = idx & 1;
            int row = row0 + r;
            uint32_t d = (uint32_t)(r * (WS3 * 2) + s * 16);
            if (row < NE) {
                const size_t gi = (size_t)row * 16 + s * 8;
                cp16(sbase + O3_AHI + d, EAhi + gi);
                cp16(sbase + O3_ALO + d, EAlo + gi);
            } else {
                uint4 z = make_uint4(0, 0, 0, 0);
                *(uint4*)(smem + O3_AHI + d) = z;
                *(uint4*)(smem + O3_ALO + d) = z;
            }
        }
    }
    asm volatile("cp.async.commit_group;");

    float acc[20][4];
#pragma unroll
    for (int t = 0; t < 20; t++)
#pragma unroll
        for (int j = 0; j < 4; j++) acc[t][j] = 0.f;

    asm volatile("cp.async.wait_group 0;");
    __syncthreads();

    const int arow = (lane & 7) + ((lane >> 3) & 1) * 8;
    const int acol = (lane >> 4) * 8;
    const uint32_t aAhi = sbase + O3_AHI + (uint32_t)((m0w + arow) * WS3 + acol) * 2;
    const uint32_t aAlo = sbase + O3_ALO + (uint32_t)((m0w + arow) * WS3 + acol) * 2;
    const int brow = (lane & 7) + ((lane >> 4) << 3);
    const int bcol = ((lane >> 3) & 1) * 8;
    const uint32_t bWhi = sbase + O3_WHI + (uint32_t)((n0w + brow) * WS3 + bcol) * 2;
    const uint32_t bWlo = sbase + O3_WLO + (uint32_t)((n0w + brow) * WS3 + bcol) * 2;

    MMA_BODY(aAhi, aAlo, bWhi, bWlo, 1, WS3)

    __syncthreads();
    float* Cs = (float*)smem;
    STAGE_ACC(Cs)
    __syncthreads();

    for (int idx = tid; idx < 128 * 20; idx += 256) {
        int r = idx / 20, u = idx - r * 20;
        int row = row0 + r;
        if (row >= NE) continue;
        float4 v0 = *reinterpret_cast<float4*>(&Cs[r * 164 + u * 8]);
        float4 v1 = *reinterpret_cast<float4*>(&Cs[r * 164 + u * 8 + 4]);
        const float* gp = P + (size_t)srcIdx[row] * DIM + u * 8;
        float4 g0 = __ldg((const float4*)gp);
        float4 g1 = __ldg((const float4*)(gp + 4));
        v0.x = fmaxf(v0.x + g0.x, 0.f); v0.y = fmaxf(v0.y + g0.y, 0.f);
        v0.z = fmaxf(v0.z + g0.z, 0.f); v0.w = fmaxf(v0.w + g0.w, 0.f);
        v1.x = fmaxf(v1.x + g1.x, 0.f); v1.y = fmaxf(v1.y + g1.y, 0.f);
        v1.z = fmaxf(v1.z + g1.z, 0.f); v1.w = fmaxf(v1.w + g1.w, 0.f);
        uint4 H, L;
        split2(v0.x, v0.y, H.x, L.x);
        split2(v0.z, v0.w, H.y, L.y);
        split2(v1.x, v1.y, H.z, L.z);
        split2(v1.z, v1.w, H.w, L.w);
        *(uint4*)&OutHi[(size_t)row * DIM + u * 8] = H;
        *(uint4*)&OutLo[(size_t)row * DIM + u * 8] = L;
        float* p = Sred + (size_t)dstIdx[row] * DIM + u * 8;
        redv4(p, v0);
        redv4(p + 4, v1);
    }
}

// ---------------- pipelined edge GEMM (R9 config, bias folded into T) ----------------
#define WS2 40
#define SSTAGE 46080
#define SOFF_WHI 0
#define SOFF_WLO 12800
#define SOFF_AHI 25600
#define SOFF_ALO 35840
#define EDGE_SMEM (2 * SSTAGE)   // 92160 B -> 2 CTAs/SM

__global__ __launch_bounds__(256, 2) void k_edge(
    const unsigned short* __restrict__ Ahi, const unsigned short* __restrict__ Alo,
    const unsigned short* __restrict__ Whi, const unsigned short* __restrict__ Wlo,
    const unsigned short* __restrict__ H0hi, const unsigned short* __restrict__ H0lo,
    const float* __restrict__ T,           // T already includes Wh_b
    const int* __restrict__ srcIdx, const int* __restrict__ dstIdx,
    unsigned short* __restrict__ OutHi, unsigned short* __restrict__ OutLo,
    float* __restrict__ Sred)
{
    extern __shared__ char smem[];
    const uint32_t sbase = cvta_s(smem);

    const int tid = threadIdx.x;
    const int lane = tid & 31, wid = tid >> 5;
    const int warp_m = wid & 3, warp_n = wid >> 2;
    const int m0w = warp_m * 32, n0w = warp_n * 80;
    const int row0 = blockIdx.x * 128;

    for (int idx = tid; idx < 640; idx += 256) {
        int r = idx / 5, s = idx - r * 5;
        int row = row0 + r;
        if (row < NE)
            prefetchL2(T + (size_t)srcIdx[row] * DIM + s * 32);
    }

    const int arow = (lane & 7) + ((lane >> 3) & 1) * 8;
    const int acol = (lane >> 4) * 8;
    const uint32_t aoff = SOFF_AHI + (uint32_t)((m0w + arow) * WS2 + acol) * 2;
    const int brow = (lane & 7) + ((lane >> 4) << 3);
    const int bcol = ((lane >> 3) & 1) * 8;
    const uint32_t boff = SOFF_WHI + (uint32_t)((n0w + brow) * WS2 + bcol) * 2;

    float acc[20][4];
#pragma unroll
    for (int t = 0; t < 20; t++)
#pragma unroll
        for (int j = 0; j < 4; j++) acc[t][j] = 0.f;

    auto load_chunk = [&](int c) {
        const uint32_t sb = sbase + (uint32_t)(c & 1) * SSTAGE;
        const int k0 = c * 32;
        for (int idx = tid; idx < 640; idx += 256) {
            int h = idx >> 2, s = idx & 3;
            uint32_t d = sb + (uint32_t)((h * WS2 + s * 8) * 2);
            const int gi = h * 160 + k0 + s * 8;
            cp16(d + SOFF_WHI, Whi + gi);
            cp16(d + SOFF_WLO, Wlo + gi);
        }
        for (int idx = tid; idx < 512; idx += 256) {
            int r = idx >> 2, s = idx & 3;
            int row = row0 + r;
            uint32_t d = sb + SOFF_AHI + (uint32_t)((r * WS2 + s * 8) * 2);
            if (row < NE) {
                const size_t gi = (size_t)row * DIM + k0 + s * 8;
                cp16(d, Ahi + gi);
                cp16(d + (SOFF_ALO - SOFF_AHI), Alo + gi);
            } else {
                size_t off = (size_t)(c & 1) * SSTAGE + SOFF_AHI + (r * WS2 + s * 8) * 2;
                uint4 z = make_uint4(0, 0, 0, 0);
                *(uint4*)(smem + off) = z;
                *(uint4*)(smem + off + (SOFF_ALO - SOFF_AHI)) = z;
            }
        }
        asm volatile("cp.async.commit_group;");
    };

    load_chunk(0);
    load_chunk(1);

#pragma unroll
    for (int c = 0; c < 5; c++) {
        if (c < 4) asm volatile("cp.async.wait_group 1;");
        else       asm volatile("cp.async.wait_group 0;");
        __syncthreads();
        const uint32_t sb = (uint32_t)(c & 1) * SSTAGE;
        const uint32_t aAhi = sbase + sb + aoff;
        const uint32_t aAlo = aAhi + (SOFF_ALO - SOFF_AHI);
        const uint32_t bWhi = sbase + sb + boff;
        const uint32_t bWlo = bWhi + (SOFF_WLO - SOFF_WHI);
        MMA_BODY(aAhi, aAlo, bWhi, bWlo, 2, WS2)
        if (c < 3) {
            __syncthreads();
            load_chunk(c + 2);
        }
    }

    __syncthreads();
    float* Cs = (float*)smem;
    STAGE_ACC(Cs)
    __syncthreads();

    // epilogue: H' = relu(recon(H0) + T'[src] - G[rev])   (bias already in T')
    for (int idx = tid; idx < 128 * 20; idx += 256) {
        int r = idx / 20, u = idx - r * 20;
        int row = row0 + r;
        if (row >= NE) continue;
        float4 g0 = *reinterpret_cast<float4*>(&Cs[(r ^ 1) * 164 + u * 8]);
        float4 g1 = *reinterpret_cast<float4*>(&Cs[(r ^ 1) * 164 + u * 8 + 4]);
        uint4 hh = *(const uint4*)&H0hi[(size_t)row * DIM + u * 8];
        uint4 hl = *(const uint4*)&H0lo[(size_t)row * DIM + u * 8];
        float2 ha = recon2(hh.x, hl.x), hb = recon2(hh.y, hl.y);
        float2 hc = recon2(hh.z, hl.z), hd = recon2(hh.w, hl.w);
        const float* tp = T + (size_t)srcIdx[row] * DIM + u * 8;
        float4 t0 = __ldg((const float4*)tp);
        float4 t1 = __ldg((const float4*)(tp + 4));
        float4 v0, v1;
        v0.x = fmaxf(ha.x + t0.x - g0.x, 0.f);
        v0.y = fmaxf(ha.y + t0.y - g0.y, 0.f);
        v0.z = fmaxf(hb.x + t0.z - g0.z, 0.f);
        v0.w = fmaxf(hb.y + t0.w - g0.w, 0.f);
        v1.x = fmaxf(hc.x + t1.x - g1.x, 0.f);
        v1.y = fmaxf(hc.y + t1.y - g1.y, 0.f);
        v1.z = fmaxf(hd.x + t1.z - g1.z, 0.f);
        v1.w = fmaxf(hd.y + t1.w - g1.w, 0.f);
        if (OutHi) {
            uint4 H, L;
            split2(v0.x, v0.y, H.x, L.x);
            split2(v0.z, v0.w, H.y, L.y);
            split2(v1.x, v1.y, H.z, L.z);
            split2(v1.z, v1.w, H.w, L.w);
            *(uint4*)&OutHi[(size_t)row * DIM + u * 8] = H;
            *(uint4*)&OutLo[(size_t)row * DIM + u * 8] = L;
        }
        float* p = Sred + (size_t)dstIdx[row] * DIM + u * 8;
        redv4(p, v0);
        redv4(p + 4, v1);
    }
}

// ---------------- where(rowsum==0, x, M) ----------------
__global__ void k_where(float* __restrict__ M, const float* __restrict__ x)
{
    int gt = blockIdx.x * blockDim.x + threadIdx.x;
    int n = gt >> 5;
    int lane = gt & 31;
    if (n >= NN) return;
    float s = 0.f;
#pragma unroll
    for (int j = 0; j < 5; j++) s += M[n * DIM + lane + j * 32];
#pragma unroll
    for (int o = 16; o; o >>= 1) s += __shfl_xor_sync(0xffffffffu, s, o);
    if (s == 0.f) {
#pragma unroll
        for (int j = 0; j < 5; j++)
            M[n * DIM + lane + j * 32] = x[n * DIM + lane + j * 32];
    }
}

// ---------------- launch ----------------
extern "C" void kernel_launch(void* const* d_in, const int* in_sizes, int n_in,
                              void* d_out, int out_size)
{
    const float* x    = (const float*)d_in[0];
    const float* ea   = (const float*)d_in[1];
    const void*  eidx = d_in[2];
    const float* Wi_w = (const float*)d_in[4];
    const float* Wi_b = (const float*)d_in[5];
    const float* Wh_w = (const float*)d_in[6];
    const float* Wh_b = (const float*)d_in[7];
    const float* Wo_w = (const float*)d_in[8];
    const float* Wo_b = (const float*)d_in[9];
    float* out = (float*)d_out;

    void *pP, *pHhi, *pHlo, *pGhi, *pGlo, *pEAhi, *pEAlo, *pS0, *pS1, *pM1, *pT, *pSrc, *pDst;
    void *pWih, *pWil, *pWhh, *pWhl, *pWoh, *pWol;
    cudaGetSymbolAddress(&pP,    g_P);
    cudaGetSymbolAddress(&pHhi,  g_Hhi);
    cudaGetSymbolAddress(&pHlo,  g_Hlo);
    cudaGetSymbolAddress(&pGhi,  g_Ghi);
    cudaGetSymbolAddress(&pGlo,  g_Glo);
    cudaGetSymbolAddress(&pEAhi, g_EAhi);
    cudaGetSymbolAddress(&pEAlo, g_EAlo);
    cudaGetSymbolAddress(&pS0,   g_S0);
    cudaGetSymbolAddress(&pS1,   g_S1);
    cudaGetSymbolAddress(&pM1,   g_M1);
    cudaGetSymbolAddress(&pT,    g_T);
    cudaGetSymbolAddress(&pSrc,  g_src);
    cudaGetSymbolAddress(&pDst,  g_dst);
    cudaGetSymbolAddress(&pWih,  g_Wih);
    cudaGetSymbolAddress(&pWil,  g_Wil);
    cudaGetSymbolAddress(&pWhh,  g_Whh);
    cudaGetSymbolAddress(&pWhl,  g_Whl);
    cudaGetSymbolAddress(&pWoh,  g_Woh);
    cudaGetSymbolAddress(&pWol,  g_Wol);

    cudaFuncSetAttribute(k_mma,  cudaFuncAttributeMaxDynamicSharedMemorySize, MMA_SMEM);
    cudaFuncSetAttribute(k_h0,   cudaFuncAttributeMaxDynamicSharedMemorySize, H0_SMEM);
    cudaFuncSetAttribute(k_edge, cudaFuncAttributeMaxDynamicSharedMemorySize, EDGE_SMEM);

    const int gridE = (NE + 127) / 128;
    const int gridN = (NN + 127) / 128;
    const int gridW = (NN * 32) / 256;

    // 1) prep: indices + zero S arrays + ea pre-split
    k_prep<<<2048, 256>>>(eidx, ea, (float*)pS0, (float*)pS1, (float*)pM1);

    // 2) weight split
    const int nsplit = 160 * 176 + 160 * 160 + 160 * 320;
    k_wsplit_all<<<(nsplit + 255) / 256, 256>>>(Wi_w, Wh_w, Wo_w);

    // 3) P = x @ Wi_x^T + Wi_b
    k_mma<<<gridN, 256, MMA_SMEM>>>(x, DIM, DIM, 0, nullptr, 0, 0, 0, 1, NN,
                                    (const unsigned short*)pWih, (const unsigned short*)pWil, 176,
                                    Wi_b, 0, (float*)pP);

    // 4) H0 pass: split store + S0 red
    k_h0<<<gridE, 256, H0_SMEM>>>((const unsigned short*)pEAhi, (const unsigned short*)pEAlo,
                                  (const unsigned short*)pWih, (const unsigned short*)pWil,
                                  (const float*)pP, (const int*)pSrc, (const int*)pDst,
                                  (unsigned short*)pHhi, (unsigned short*)pHlo,
                                  (float*)pS0);

    // 5) T = S0 @ Wh^T + Wh_b   (bias folded here)
    k_mma<<<gridN, 256, MMA_SMEM>>>((const float*)pS0, DIM, DIM, 0, nullptr, 0, 0, 0, 1, NN,
                                    (const unsigned short*)pWhh, (const unsigned short*)pWhl, DIM,
                                    Wh_b, 0, (float*)pT);

    // 6) iter1
    k_edge<<<gridE, 256, EDGE_SMEM>>>((const unsigned short*)pHhi, (const unsigned short*)pHlo,
                                      (const unsigned short*)pWhh, (const unsigned short*)pWhl,
                                      (const unsigned short*)pHhi, (const unsigned short*)pHlo,
                                      (const float*)pT,
                                      (const int*)pSrc, (const int*)pDst,
                                      (unsigned short*)pGhi, (unsigned short*)pGlo,
                                      (float*)pS1);

    // 7) T = S1 @ Wh^T + Wh_b
    k_mma<<<gridN, 256, MMA_SMEM>>>((const float*)pS1, DIM, DIM, 0, nullptr, 0, 0, 0, 1, NN,
                                    (const unsigned short*)pWhh, (const unsigned short*)pWhl, DIM,
                                    Wh_b, 0, (float*)pT);

    // 8) iter2
    k_edge<<<gridE, 256, EDGE_SMEM>>>((const unsigned short*)pGhi, (const unsigned short*)pGlo,
                                      (const unsigned short*)pWhh, (const unsigned short*)pWhl,
                                      (const unsigned short*)pHhi, (const unsigned short*)pHlo,
                                      (const float*)pT,
                                      (const int*)pSrc, (const int*)pDst,
                                      nullptr, nullptr,
                                      (float*)pM1);

    // 9) where
    k_where<<<gridW, 256>>>((float*)pM1, x);

    // 10) out = relu([x ; M1] @ Wo^T + Wo_b)
    k_mma<<<gridN, 256, MMA_SMEM>>>(x, DIM, DIM, 0, (const float*)pM1, DIM, DIM, DIM, 2, NN,
                                    (const unsigned short*)pWoh, (const unsigned short*)pWol, 2 * DIM,
                                    Wo_b, 1, out);
}

// round 12
// speedup vs baseline: 1.0791x; 1.0052x over previous
#include <cuda_runtime.h>
#include <cstdint>

#define NN 50000
#define NE 500000
#define DIM 160
#define BOND 14
#define WS 88   // k_mma padded k-stride (bf16); 176B rows, conflict-free ldsm

// ---------------- scratch ----------------
__device__ int   g_src[NE];
__device__ int   g_dst[NE];
__device__ float g_P [NN * DIM];
__device__ unsigned short g_Hhi[NE * DIM], g_Hlo[NE * DIM];   // H0 split-bf16
__device__ unsigned short g_Ghi[NE * DIM], g_Glo[NE * DIM];   // H1 split-bf16
__device__ unsigned short g_EAhi[NE * 16], g_EAlo[NE * 16];   // padded split ea [NE,16]
__device__ float g_S0[NN * DIM];
__device__ float g_S1[NN * DIM];
__device__ float g_M1[NN * DIM];
__device__ float g_T [NN * DIM];
__device__ unsigned short g_Wih[160 * 176], g_Wil[160 * 176];
__device__ unsigned short g_Whh[160 * 160], g_Whl[160 * 160];
__device__ unsigned short g_Woh[160 * 320], g_Wol[160 * 320];

// ---------------- helpers ----------------
__device__ __forceinline__ uint32_t cvta_s(const void* p) {
    uint32_t r;
    asm("{ .reg .u64 t; cvta.to.shared.u64 t, %1; cvt.u32.u64 %0, t; }" : "=r"(r) : "l"(p));
    return r;
}
__device__ __forceinline__ void ldsm4(uint32_t (&r)[4], uint32_t addr) {
    asm volatile("ldmatrix.sync.aligned.m8n8.x4.shared.b16 {%0,%1,%2,%3}, [%4];"
                 : "=r"(r[0]), "=r"(r[1]), "=r"(r[2]), "=r"(r[3]) : "r"(addr));
}
__device__ __forceinline__ void mma16816(float* c, const uint32_t (&a)[4],
                                         uint32_t b0, uint32_t b1) {
    asm volatile("mma.sync.aligned.m16n8k16.row.col.f32.bf16.bf16.f32 "
                 "{%0,%1,%2,%3},{%4,%5,%6,%7},{%8,%9},{%0,%1,%2,%3};"
                 : "+f"(c[0]), "+f"(c[1]), "+f"(c[2]), "+f"(c[3])
                 : "r"(a[0]), "r"(a[1]), "r"(a[2]), "r"(a[3]), "r"(b0), "r"(b1));
}
__device__ __forceinline__ void split2(float x, float y, uint32_t& hi2, uint32_t& lo2) {
    uint32_t ux = __float_as_uint(x), uy = __float_as_uint(y);
    hi2 = __byte_perm(ux, uy, 0x7632);
    float lx = x - __uint_as_float(ux & 0xffff0000u);
    float ly = y - __uint_as_float(uy & 0xffff0000u);
    asm("cvt.rn.bf16x2.f32 %0, %1, %2;" : "=r"(lo2) : "f"(ly), "f"(lx));
}
__device__ __forceinline__ float2 recon2(uint32_t hi2, uint32_t lo2) {
    float2 r;
    r.x = __uint_as_float(hi2 << 16) + __uint_as_float(lo2 << 16);
    r.y = __uint_as_float(hi2 & 0xffff0000u) + __uint_as_float(lo2 & 0xffff0000u);
    return r;
}
__device__ __forceinline__ void cp16(uint32_t dst, const void* src) {
    asm volatile("cp.async.cg.shared.global [%0], [%1], 16;" :: "r"(dst), "l"(src));
}
__device__ __forceinline__ void redv4(float* p, float4 v) {
    asm volatile("red.global.add.v4.f32 [%0], {%1,%2,%3,%4};"
                 :: "l"(p), "f"(v.x), "f"(v.y), "f"(v.z), "f"(v.w) : "memory");
}
__device__ __forceinline__ void prefetchL2(const void* p) {
    asm volatile("prefetch.global.L2 [%0];" :: "l"(p));
}

// ---------------- prep: indices + zero + ea pre-split ----------------
__global__ void k_prep(const void* ei, const float* __restrict__ ea,
                       float* S0, float* S1, float* M1) {
    __shared__ int s64;
    if (threadIdx.x < 32) {
        const unsigned long long* p = (const unsigned long long*)ei;
        int bad = 0;
        for (int j = threadIdx.x; j < 1024; j += 32)
            if (p[j] >= (unsigned long long)NN) bad = 1;
        unsigned m = __ballot_sync(0xffffffffu, bad);
        if (threadIdx.x == 0) s64 = (m == 0u);
    }
    __syncthreads();
    const int is64 = s64;
    const int gstride = gridDim.x * blockDim.x;
    int g = blockIdx.x * blockDim.x + threadIdx.x;
    for (int i = g; i < NE; i += gstride) {
        if (is64) {
            const long long* p = (const long long*)ei;
            g_src[i] = (int)p[i];
            g_dst[i] = (int)p[NE + i];
        } else {
            const int* p = (const int*)ei;
            g_src[i] = p[i];
            g_dst[i] = p[NE + i];
        }
    }
    const int nz = NN * DIM / 4;
    float4 z = make_float4(0.f, 0.f, 0.f, 0.f);
    for (int i = g; i < nz; i += gstride) {
        reinterpret_cast<float4*>(S0)[i] = z;
        reinterpret_cast<float4*>(S1)[i] = z;
        reinterpret_cast<float4*>(M1)[i] = z;
    }
    uint32_t* eh = (uint32_t*)g_EAhi;
    uint32_t* el = (uint32_t*)g_EAlo;
    for (int i = g; i < NE * 8; i += gstride) {
        int e = i >> 3, c2 = (i & 7) << 1;
        float2 f = (c2 < BOND) ? *(const float2*)(ea + (size_t)e * BOND + c2)
                               : make_float2(0.f, 0.f);
        uint32_t h2, l2;
        split2(f.x, f.y, h2, l2);
        eh[i] = h2;
        el[i] = l2;
    }
}

// ---------------- weight split ----------------
__global__ void k_wsplit_all(const float* __restrict__ wi, const float* __restrict__ wh,
                             const float* __restrict__ wo) {
    int i = blockIdx.x * blockDim.x + threadIdx.x;
    const int nWi = 160 * 176, nWh = 160 * 160, nWo = 160 * 320;
    float f;
    unsigned short* hi;
    unsigned short* lo;
    int oi;
    if (i < nWi) {
        int h = i / 176, c = i - h * 176;
        f = (c < 174) ? wi[h * 174 + c] : 0.f;
        hi = g_Wih; lo = g_Wil; oi = i;
    } else if (i < nWi + nWh) {
        oi = i - nWi;
        f = wh[oi];
        hi = g_Whh; lo = g_Whl;
    } else if (i < nWi + nWh + nWo) {
        oi = i - nWi - nWh;
        f = wo[oi];
        hi = g_Woh; lo = g_Wol;
    } else return;
    uint32_t u = __float_as_uint(f);
    hi[oi] = (unsigned short)(u >> 16);
    float lf = f - __uint_as_float(u & 0xffff0000u);
    unsigned short ls;
    asm("cvt.rn.bf16.f32 %0, %1;" : "=h"(ls) : "f"(lf));
    lo[oi] = ls;
}

// ---------------- k_mma smem layout ----------------
#define OFF_WHI 0
#define OFF_WLO (160 * WS * 2)
#define OFF_AHI (2 * 160 * WS * 2)
#define OFF_ALO (2 * 160 * WS * 2 + 128 * WS * 2)
#define MMA_SMEM (2 * 160 * WS * 2 + 2 * 128 * WS * 2)   // 101376 B

#define MMA_BODY(aAhi, aAlo, bWhi, bWlo, ksteps, ws)                               \
    for (int ks = 0; ks < (ksteps); ks++) {                                        \
        const uint32_t ko = (uint32_t)ks * 32;                                     \
        uint32_t ah0[4], ah1[4], al0[4], al1[4];                                   \
        ldsm4(ah0, (aAhi) + ko);                                                   \
        ldsm4(ah1, (aAhi) + ko + 16 * (ws) * 2);                                   \
        ldsm4(al0, (aAlo) + ko);                                                   \
        ldsm4(al1, (aAlo) + ko + 16 * (ws) * 2);                                   \
        _Pragma("unroll")                                                          \
        for (int p = 0; p < 5; p++) {                                              \
            const uint32_t bo = ko + (uint32_t)p * (16 * (ws) * 2);                \
            uint32_t bh[4], bl[4];                                                 \
            ldsm4(bh, (bWhi) + bo);                                                \
            ldsm4(bl, (bWlo) + bo);                                                \
            mma16816(acc[2 * p],      ah0, bh[0], bh[1]);                          \
            mma16816(acc[2 * p],      ah0, bl[0], bl[1]);                          \
            mma16816(acc[2 * p],      al0, bh[0], bh[1]);                          \
            mma16816(acc[2 * p + 1],  ah0, bh[2], bh[3]);                          \
            mma16816(acc[2 * p + 1],  ah0, bl[2], bl[3]);                          \
            mma16816(acc[2 * p + 1],  al0, bh[2], bh[3]);                          \
            mma16816(acc[10 + 2 * p],     ah1, bh[0], bh[1]);                      \
            mma16816(acc[10 + 2 * p],     ah1, bl[0], bl[1]);                      \
            mma16816(acc[10 + 2 * p],     al1, bh[0], bh[1]);                      \
            mma16816(acc[10 + 2 * p + 1], ah1, bh[2], bh[3]);                      \
            mma16816(acc[10 + 2 * p + 1], ah1, bl[2], bl[3]);                      \
            mma16816(acc[10 + 2 * p + 1], al1, bh[2], bh[3]);                      \
        }                                                                          \
    }

#define STAGE_ACC(Cs)                                                              \
    {                                                                              \
        const int rf = m0w + (lane >> 2);                                          \
        const int cf = n0w + (lane & 3) * 2;                                       \
        _Pragma("unroll")                                                          \
        for (int mt = 0; mt < 2; mt++)                                             \
            _Pragma("unroll")                                                      \
            for (int half = 0; half < 2; half++) {                                 \
                int rr = rf + mt * 16 + half * 8;                                  \
                _Pragma("unroll")                                                  \
                for (int nt = 0; nt < 10; nt++) {                                  \
                    float* pp = &(Cs)[rr * 164 + cf + nt * 8];                     \
                    pp[0] = acc[mt * 10 + nt][half * 2 + 0];                       \
                    pp[1] = acc[mt * 10 + nt][half * 2 + 1];                       \
                }                                                                  \
            }                                                                      \
    }

// ---------------- generic GEMM (P, T, out) ----------------
__global__ __launch_bounds__(256, 2) void k_mma(
    const float* __restrict__ A0, int lda0, int klen0, int wk0,
    const float* __restrict__ A1, int lda1, int klen1, int wk1,
    int nph, int M,
    const unsigned short* __restrict__ Whi, const unsigned short* __restrict__ Wlo, int ldw,
    const float* __restrict__ bias, int dorelu,
    float* __restrict__ Cout)
{
    extern __shared__ char smem[];
    unsigned short* Whi_s = (unsigned short*)(smem + OFF_WHI);
    unsigned short* Wlo_s = (unsigned short*)(smem + OFF_WLO);
    unsigned short* Ahi_s = (unsigned short*)(smem + OFF_AHI);
    unsigned short* Alo_s = (unsigned short*)(smem + OFF_ALO);
    const uint32_t sbase = cvta_s(smem);

    const int tid = threadIdx.x;
    const int lane = tid & 31, wid = tid >> 5;
    const int warp_m = wid & 3, warp_n = wid >> 2;
    const int m0w = warp_m * 32, n0w = warp_n * 80;
    const int row0 = blockIdx.x * 128;

    const int arow = (lane & 7) + ((lane >> 3) & 1) * 8;
    const int acol = (lane >> 4) * 8;
    const uint32_t aAhi = sbase + OFF_AHI + (uint32_t)((m0w + arow) * WS + acol) * 2;
    const uint32_t aAlo = sbase + OFF_ALO + (uint32_t)((m0w + arow) * WS + acol) * 2;
    const int brow = (lane & 7) + ((lane >> 4) << 3);
    const int bcol = ((lane >> 3) & 1) * 8;
    const uint32_t bWhi = sbase + OFF_WHI + (uint32_t)((n0w + brow) * WS + bcol) * 2;
    const uint32_t bWlo = sbase + OFF_WLO + (uint32_t)((n0w + brow) * WS + bcol) * 2;

    float acc[20][4];
#pragma unroll
    for (int t = 0; t < 20; t++)
#pragma unroll
        for (int j = 0; j < 4; j++) acc[t][j] = 0.f;

    for (int ph = 0; ph < nph; ph++) {
        const float* A = (ph == 0) ? A0 : A1;
        const int lda  = (ph == 0) ? lda0 : lda1;
        const int klen = (ph == 0) ? klen0 : klen1;
        const int wk   = (ph == 0) ? wk0 : wk1;
        const int nch = (klen + 79) / 80;

        for (int c = 0; c < nch; c++) {
            const int k0g = c * 80;
            const int kc = min(80, klen - k0g);
            const bool cpW = (kc == 80) && ((ldw & 7) == 0) && (((wk + k0g) & 7) == 0);
            __syncthreads();

            if (cpW) {
                for (int idx = tid; idx < 160 * 10; idx += 256) {
                    int h = idx / 10, s = idx - h * 10;
                    uint32_t d = (uint32_t)((h * WS + s * 8) * 2);
                    const int gi = h * ldw + wk + k0g + s * 8;
                    cp16(sbase + OFF_WHI + d, Whi + gi);
                    cp16(sbase + OFF_WLO + d, Wlo + gi);
                }
                asm volatile("cp.async.commit_group;");
            } else {
                const int kpad = (kc + 15) & ~15;
                for (int idx = tid; idx < 160 * kpad; idx += 256) {
                    int h = idx / kpad, kk = idx - h * kpad;
                    unsigned short vh = 0, vl = 0;
                    if (kk < kc) {
                        int gi = h * ldw + wk + k0g + kk;
                        vh = Whi[gi]; vl = Wlo[gi];
                    }
                    Whi_s[h * WS + kk] = vh;
                    Wlo_s[h * WS + kk] = vl;
                }
            }

            if (kc == 80 && (lda & 3) == 0) {
                for (int idx = tid; idx < 128 * 20; idx += 256) {
                    int r = idx / 20, q = idx - r * 20;
                    int row = row0 + r;
                    float4 v = make_float4(0.f, 0.f, 0.f, 0.f);
                    if (row < M)
                        v = *reinterpret_cast<const float4*>(A + (size_t)row * lda + k0g + q * 4);
                    uint32_t h2a, l2a, h2b, l2b;
                    split2(v.x, v.y, h2a, l2a);
                    split2(v.z, v.w, h2b, l2b);
                    *(uint2*)&Ahi_s[r * WS + q * 4] = make_uint2(h2a, h2b);
                    *(uint2*)&Alo_s[r * WS + q * 4] = make_uint2(l2a, l2b);
                }
            } else {
                const int kpad = (kc + 15) & ~15;
                for (int idx = tid; idx < 128 * kpad; idx += 256) {
                    int r = idx / kpad, kk = idx - r * kpad;
                    int row = row0 + r;
                    float f = 0.f;
                    if (row < M && kk < kc) f = A[(size_t)row * lda + k0g + kk];
                    uint32_t u = __float_as_uint(f);
                    Ahi_s[r * WS + kk] = (unsigned short)(u >> 16);
                    float lf = f - __uint_as_float(u & 0xffff0000u);
                    unsigned short ls;
                    asm("cvt.rn.bf16.f32 %0, %1;" : "=h"(ls) : "f"(lf));
                    Alo_s[r * WS + kk] = ls;
                }
            }

            if (cpW) asm volatile("cp.async.wait_group 0;");
            __syncthreads();

            const int ksteps = ((kc + 15) & ~15) >> 4;
            MMA_BODY(aAhi, aAlo, bWhi, bWlo, ksteps, WS)
        }
    }

    __syncthreads();
    float* Cs = (float*)smem;
    STAGE_ACC(Cs)
    __syncthreads();

#pragma unroll
    for (int idx = tid; idx < 128 * 20; idx += 256) {
        int r = idx / 20, u = idx - r * 20;
        int row = row0 + r;
        if (row >= M) continue;
        float4 v0 = *reinterpret_cast<float4*>(&Cs[r * 164 + u * 8]);
        float4 v1 = *reinterpret_cast<float4*>(&Cs[r * 164 + u * 8 + 4]);
        if (bias) {
            float4 b0 = __ldg((const float4*)(bias + u * 8));
            float4 b1 = __ldg((const float4*)(bias + u * 8 + 4));
            v0.x += b0.x; v0.y += b0.y; v0.z += b0.z; v0.w += b0.w;
            v1.x += b1.x; v1.y += b1.y; v1.z += b1.z; v1.w += b1.w;
        }
        if (dorelu) {
            v0.x = fmaxf(v0.x, 0.f); v0.y = fmaxf(v0.y, 0.f);
            v0.z = fmaxf(v0.z, 0.f); v0.w = fmaxf(v0.w, 0.f);
            v1.x = fmaxf(v1.x, 0.f); v1.y = fmaxf(v1.y, 0.f);
            v1.z = fmaxf(v1.z, 0.f); v1.w = fmaxf(v1.w, 0.f);
        }
        float4* cp = (float4*)(Cout + (size_t)row * DIM + u * 8);
        cp[0] = v0; cp[1] = v1;
    }
}

// ---------------- dedicated H0 kernel: M=64 tiles, 3 CTAs/SM ----------------
// 8 warps = 4(m) x 2(n); warp tile 16x80; acc[10][4].
#define WS3 24
#define O3_WHI 0
#define O3_WLO 7680
#define O3_AHI 15360
#define O3_ALO 18432
#define H0_SMEM (64 * 164 * 4)   // 41984 B

#define MMA16_BODY(aAhi, aAlo, bWhi, bWlo, ksteps, ws)                             \
    for (int ks = 0; ks < (ksteps); ks++) {                                        \
        const uint32_t ko = (uint32_t)ks * 32;                                     \
        uint32_t ah[4], al[4];                                                     \
        ldsm4(ah, (aAhi) + ko);                                                    \
        ldsm4(al, (aAlo) + ko);                                                    \
        _Pragma("unroll")                                                          \
        for (int p = 0; p < 5; p++) {                                              \
            const uint32_t bo = ko + (uint32_t)p * (16 * (ws) * 2);                \
            uint32_t bh[4], bl[4];                                                 \
            ldsm4(bh, (bWhi) + bo);                                                \
            ldsm4(bl, (bWlo) + bo);                                                \
            mma16816(acc[2 * p],     ah, bh[0], bh[1]);                            \
            mma16816(acc[2 * p],     ah, bl[0], bl[1]);                            \
            mma16816(acc[2 * p],     al, bh[0], bh[1]);                            \
            mma16816(acc[2 * p + 1], ah, bh[2], bh[3]);                            \
            mma16816(acc[2 * p + 1], ah, bl[2], bl[3]);                            \
            mma16816(acc[2 * p + 1], al, bh[2], bh[3]);                            \
        }                                                                          \
    }

__global__ __launch_bounds__(256, 3) void k_h0(
    const unsigned short* __restrict__ EAhi, const unsigned short* __restrict__ EAlo,
    const unsigned short* __restrict__ Whi, const unsigned short* __restrict__ Wlo,
    const float* __restrict__ P,
    const int* __restrict__ srcIdx, const int* __restrict__ dstIdx,
    unsigned short* __restrict__ OutHi, unsigned short* __restrict__ OutLo,
    float* __restrict__ Sred)
{
    extern __shared__ char smem[];
    const uint32_t sbase = cvta_s(smem);
    const int tid = threadIdx.x;
    const int lane = tid & 31, wid = tid >> 5;
    const int warp_m = wid & 3, warp_n = wid >> 2;
    const int m0w = warp_m * 16, n0w = warp_n * 80;
    const int row0 = blockIdx.x * 64;

    // prefetch gathered P rows into L2 (64 rows x 5 segs)
    for (int idx = tid; idx < 320; idx += 256) {
        int r = idx / 5, s = idx - r * 5;
        int row = row0 + r;
        if (row < NE)
            prefetchL2(P + (size_t)srcIdx[row] * DIM + s * 32);
    }

    // W slice (cols 160..175 of stride-176 array): 160 rows x 32B
    for (int idx = tid; idx < 320; idx += 256) {
        int h = idx >> 1, s = idx & 1;
        uint32_t d = (uint32_t)(h * (WS3 * 2) + s * 16);
        const int gi = h * 176 + 160 + s * 8;
        cp16(sbase + O3_WHI + d, Whi + gi);
        cp16(sbase + O3_WLO + d, Wlo + gi);
    }
    // A: 64 rows x 32B (pre-split ea)
    if (tid < 128) {
        int r = tid >> 1, s = tid & 1;
        int row = row0 + r;
        uint32_t d = (uint32_t)(r * (WS3 * 2) + s * 16);
        if (row < NE) {
            const size_t gi = (size_t)row * 16 + s * 8;
            cp16(sbase + O3_AHI + d, EAhi + gi);
            cp16(sbase + O3_ALO + d, EAlo + gi);
        } else {
            uint4 z = make_uint4(0, 0, 0, 0);
            *(uint4*)(smem + O3_AHI + d) = z;
            *(uint4*)(smem + O3_ALO + d) = z;
        }
    }
    asm volatile("cp.async.commit_group;");

    float acc[10][4];
#pragma unroll
    for (int t = 0; t < 10; t++)
#pragma unroll
        for (int j = 0; j < 4; j++) acc[t][j] = 0.f;

    asm volatile("cp.async.wait_group 0;");
    __syncthreads();

    const int arow = (lane & 7) + ((lane >> 3) & 1) * 8;
    const int acol = (lane >> 4) * 8;
    const uint32_t aAhi = sbase + O3_AHI + (uint32_t)((m0w + arow) * WS3 + acol) * 2;
    const uint32_t aAlo = sbase + O3_ALO + (uint32_t)((m0w + arow) * WS3 + acol) * 2;
    const int brow = (lane & 7) + ((lane >> 4) << 3);
    const int bcol = ((lane >> 3) & 1) * 8;
    const uint32_t bWhi = sbase + O3_WHI + (uint32_t)((n0w + brow) * WS3 + bcol) * 2;
    const uint32_t bWlo = sbase + O3_WLO + (uint32_t)((n0w + brow) * WS3 + bcol) * 2;

    MMA16_BODY(aAhi, aAlo, bWhi, bWlo, 1, WS3)

    __syncthreads();
    float* Cs = (float*)smem;
    {
        const int rf = m0w + (lane >> 2);
        const int cf = n0w + (lane & 3) * 2;
#pragma unroll
        for (int half = 0; half < 2; half++) {
            int rr = rf + half * 8;
#pragma unroll
            for (int nt = 0; nt < 10; nt++) {
                float* pp = &Cs[rr * 164 + cf + nt * 8];
                pp[0] = acc[nt][half * 2 + 0];
                pp[1] = acc[nt][half * 2 + 1];
            }
        }
    }
    __syncthreads();

#pragma unroll
    for (int idx = tid; idx < 64 * 20; idx += 256) {
        int r = idx / 20, u = idx - r * 20;
        int row = row0 + r;
        if (row >= NE) continue;
        float4 v0 = *reinterpret_cast<float4*>(&Cs[r * 164 + u * 8]);
        float4 v1 = *reinterpret_cast<float4*>(&Cs[r * 164 + u * 8 + 4]);
        const float* gp = P + (size_t)srcIdx[row] * DIM + u * 8;
        float4 g0 = __ldg((const float4*)gp);
        float4 g1 = __ldg((const float4*)(gp + 4));
        v0.x = fmaxf(v0.x + g0.x, 0.f); v0.y = fmaxf(v0.y + g0.y, 0.f);
        v0.z = fmaxf(v0.z + g0.z, 0.f); v0.w = fmaxf(v0.w + g0.w, 0.f);
        v1.x = fmaxf(v1.x + g1.x, 0.f); v1.y = fmaxf(v1.y + g1.y, 0.f);
        v1.z = fmaxf(v1.z + g1.z, 0.f); v1.w = fmaxf(v1.w + g1.w, 0.f);
        uint4 H, L;
        split2(v0.x, v0.y, H.x, L.x);
        split2(v0.z, v0.w, H.y, L.y);
        split2(v1.x, v1.y, H.z, L.z);
        split2(v1.z, v1.w, H.w, L.w);
        *(uint4*)&OutHi[(size_t)row * DIM + u * 8] = H;
        *(uint4*)&OutLo[(size_t)row * DIM + u * 8] = L;
        float* p = Sred + (size_t)dstIdx[row] * DIM + u * 8;
        redv4(p, v0);
        redv4(p + 4, v1);
    }
}

// ---------------- pipelined edge GEMM (bias folded into T) ----------------
#define WS2 40
#define SSTAGE 46080
#define SOFF_WHI 0
#define SOFF_WLO 12800
#define SOFF_AHI 25600
#define SOFF_ALO 35840
#define EDGE_SMEM (2 * SSTAGE)   // 92160 B -> 2 CTAs/SM

__global__ __launch_bounds__(256, 2) void k_edge(
    const unsigned short* __restrict__ Ahi, const unsigned short* __restrict__ Alo,
    const unsigned short* __restrict__ Whi, const unsigned short* __restrict__ Wlo,
    const unsigned short* __restrict__ H0hi, const unsigned short* __restrict__ H0lo,
    const float* __restrict__ T,           // T already includes Wh_b
    const int* __restrict__ srcIdx, const int* __restrict__ dstIdx,
    unsigned short* __restrict__ OutHi, unsigned short* __restrict__ OutLo,
    float* __restrict__ Sred)
{
    extern __shared__ char smem[];
    const uint32_t sbase = cvta_s(smem);

    const int tid = threadIdx.x;
    const int lane = tid & 31, wid = tid >> 5;
    const int warp_m = wid & 3, warp_n = wid >> 2;
    const int m0w = warp_m * 32, n0w = warp_n * 80;
    const int row0 = blockIdx.x * 128;

    // prefetch gathered T rows into L2
    for (int idx = tid; idx < 640; idx += 256) {
        int r = idx / 5, s = idx - r * 5;
        int row = row0 + r;
        if (row < NE)
            prefetchL2(T + (size_t)srcIdx[row] * DIM + s * 32);
    }
    // prefetch H0 rows (sequential) when distinct from A (edge2 case)
    if (H0hi != Ahi) {
        const int nb = (min(128, NE - row0)) * (DIM * 2);   // bytes per array
        const char* ph = (const char*)(H0hi + (size_t)row0 * DIM);
        const char* pl = (const char*)(H0lo + (size_t)row0 * DIM);
        for (int idx = tid; idx * 128 < nb; idx += 256) {
            prefetchL2(ph + idx * 128);
            prefetchL2(pl + idx * 128);
        }
    }

    const int arow = (lane & 7) + ((lane >> 3) & 1) * 8;
    const int acol = (lane >> 4) * 8;
    const uint32_t aoff = SOFF_AHI + (uint32_t)((m0w + arow) * WS2 + acol) * 2;
    const int brow = (lane & 7) + ((lane >> 4) << 3);
    const int bcol = ((lane >> 3) & 1) * 8;
    const uint32_t boff = SOFF_WHI + (uint32_t)((n0w + brow) * WS2 + bcol) * 2;

    float acc[20][4];
#pragma unroll
    for (int t = 0; t < 20; t++)
#pragma unroll
        for (int j = 0; j < 4; j++) acc[t][j] = 0.f;

    auto load_chunk = [&](int c) {
        const uint32_t sb = sbase + (uint32_t)(c & 1) * SSTAGE;
        const int k0 = c * 32;
        for (int idx = tid; idx < 640; idx += 256) {
            int h = idx >> 2, s = idx & 3;
            uint32_t d = sb + (uint32_t)((h * WS2 + s * 8) * 2);
            const int gi = h * 160 + k0 + s * 8;
            cp16(d + SOFF_WHI, Whi + gi);
            cp16(d + SOFF_WLO, Wlo + gi);
        }
        for (int idx = tid; idx < 512; idx += 256) {
            int r = idx >> 2, s = idx & 3;
            int row = row0 + r;
            uint32_t d = sb + SOFF_AHI + (uint32_t)((r * WS2 + s * 8) * 2);
            if (row < NE) {
                const size_t gi = (size_t)row * DIM + k0 + s * 8;
                cp16(d, Ahi + gi);
                cp16(d + (SOFF_ALO - SOFF_AHI), Alo + gi);
            } else {
                size_t off = (size_t)(c & 1) * SSTAGE + SOFF_AHI + (r * WS2 + s * 8) * 2;
                uint4 z = make_uint4(0, 0, 0, 0);
                *(uint4*)(smem + off) = z;
                *(uint4*)(smem + off + (SOFF_ALO - SOFF_AHI)) = z;
            }
        }
        asm volatile("cp.async.commit_group;");
    };

    load_chunk(0);
    load_chunk(1);

#pragma unroll
    for (int c = 0; c < 5; c++) {
        if (c < 4) asm volatile("cp.async.wait_group 1;");
        else       asm volatile("cp.async.wait_group 0;");
        __syncthreads();
        const uint32_t sb = (uint32_t)(c & 1) * SSTAGE;
        const uint32_t aAhi = sbase + sb + aoff;
        const uint32_t aAlo = aAhi + (SOFF_ALO - SOFF_AHI);
        const uint32_t bWhi = sbase + sb + boff;
        const uint32_t bWlo = bWhi + (SOFF_WLO - SOFF_WHI);
        MMA_BODY(aAhi, aAlo, bWhi, bWlo, 2, WS2)
        if (c < 3) {
            __syncthreads();
            load_chunk(c + 2);
        }
    }

    __syncthreads();
    float* Cs = (float*)smem;
    STAGE_ACC(Cs)
    __syncthreads();

    // epilogue: H' = relu(recon(H0) + T'[src] - G[rev])   (bias already in T')
#pragma unroll
    for (int idx = tid; idx < 128 * 20; idx += 256) {
        int r = idx / 20, u = idx - r * 20;
        int row = row0 + r;
        if (row >= NE) continue;
        float4 g0 = *reinterpret_cast<float4*>(&Cs[(r ^ 1) * 164 + u * 8]);
        float4 g1 = *reinterpret_cast<float4*>(&Cs[(r ^ 1) * 164 + u * 8 + 4]);
        uint4 hh = *(const uint4*)&H0hi[(size_t)row * DIM + u * 8];
        uint4 hl = *(const uint4*)&H0lo[(size_t)row * DIM + u * 8];
        float2 ha = recon2(hh.x, hl.x), hb = recon2(hh.y, hl.y);
        float2 hc = recon2(hh.z, hl.z), hd = recon2(hh.w, hl.w);
        const float* tp = T + (size_t)srcIdx[row] * DIM + u * 8;
        float4 t0 = __ldg((const float4*)tp);
        float4 t1 = __ldg((const float4*)(tp + 4));
        float4 v0, v1;
        v0.x = fmaxf(ha.x + t0.x - g0.x, 0.f);
        v0.y = fmaxf(ha.y + t0.y - g0.y, 0.f);
        v0.z = fmaxf(hb.x + t0.z - g0.z, 0.f);
        v0.w = fmaxf(hb.y + t0.w - g0.w, 0.f);
        v1.x = fmaxf(hc.x + t1.x - g1.x, 0.f);
        v1.y = fmaxf(hc.y + t1.y - g1.y, 0.f);
        v1.z = fmaxf(hd.x + t1.z - g1.z, 0.f);
        v1.w = fmaxf(hd.y + t1.w - g1.w, 0.f);
        if (OutHi) {
            uint4 H, L;
            split2(v0.x, v0.y, H.x, L.x);
            split2(v0.z, v0.w, H.y, L.y);
            split2(v1.x, v1.y, H.z, L.z);
            split2(v1.z, v1.w, H.w, L.w);
            *(uint4*)&OutHi[(size_t)row * DIM + u * 8] = H;
            *(uint4*)&OutLo[(size_t)row * DIM + u * 8] = L;
        }
        float* p = Sred + (size_t)dstIdx[row] * DIM + u * 8;
        redv4(p, v0);
        redv4(p + 4, v1);
    }
}

// ---------------- where(rowsum==0, x, M) ----------------
__global__ void k_where(float* __restrict__ M, const float* __restrict__ x)
{
    int gt = blockIdx.x * blockDim.x + threadIdx.x;
    int n = gt >> 5;
    int lane = gt & 31;
    if (n >= NN) return;
    float s = 0.f;
#pragma unroll
    for (int j = 0; j < 5; j++) s += M[n * DIM + lane + j * 32];
#pragma unroll
    for (int o = 16; o; o >>= 1) s += __shfl_xor_sync(0xffffffffu, s, o);
    if (s == 0.f) {
#pragma unroll
        for (int j = 0; j < 5; j++)
            M[n * DIM + lane + j * 32] = x[n * DIM + lane + j * 32];
    }
}

// ---------------- launch ----------------
extern "C" void kernel_launch(void* const* d_in, const int* in_sizes, int n_in,
                              void* d_out, int out_size)
{
    const float* x    = (const float*)d_in[0];
    const float* ea   = (const float*)d_in[1];
    const void*  eidx = d_in[2];
    const float* Wi_w = (const float*)d_in[4];
    const float* Wi_b = (const float*)d_in[5];
    const float* Wh_w = (const float*)d_in[6];
    const float* Wh_b = (const float*)d_in[7];
    const float* Wo_w = (const float*)d_in[8];
    const float* Wo_b = (const float*)d_in[9];
    float* out = (float*)d_out;

    void *pP, *pHhi, *pHlo, *pGhi, *pGlo, *pEAhi, *pEAlo, *pS0, *pS1, *pM1, *pT, *pSrc, *pDst;
    void *pWih, *pWil, *pWhh, *pWhl, *pWoh, *pWol;
    cudaGetSymbolAddress(&pP,    g_P);
    cudaGetSymbolAddress(&pHhi,  g_Hhi);
    cudaGetSymbolAddress(&pHlo,  g_Hlo);
    cudaGetSymbolAddress(&pGhi,  g_Ghi);
    cudaGetSymbolAddress(&pGlo,  g_Glo);
    cudaGetSymbolAddress(&pEAhi, g_EAhi);
    cudaGetSymbolAddress(&pEAlo, g_EAlo);
    cudaGetSymbolAddress(&pS0,   g_S0);
    cudaGetSymbolAddress(&pS1,   g_S1);
    cudaGetSymbolAddress(&pM1,   g_M1);
    cudaGetSymbolAddress(&pT,    g_T);
    cudaGetSymbolAddress(&pSrc,  g_src);
    cudaGetSymbolAddress(&pDst,  g_dst);
    cudaGetSymbolAddress(&pWih,  g_Wih);
    cudaGetSymbolAddress(&pWil,  g_Wil);
    cudaGetSymbolAddress(&pWhh,  g_Whh);
    cudaGetSymbolAddress(&pWhl,  g_Whl);
    cudaGetSymbolAddress(&pWoh,  g_Woh);
    cudaGetSymbolAddress(&pWol,  g_Wol);

    cudaFuncSetAttribute(k_mma,  cudaFuncAttributeMaxDynamicSharedMemorySize, MMA_SMEM);
    cudaFuncSetAttribute(k_h0,   cudaFuncAttributeMaxDynamicSharedMemorySize, H0_SMEM);
    cudaFuncSetAttribute(k_edge, cudaFuncAttributeMaxDynamicSharedMemorySize, EDGE_SMEM);

    const int gridE  = (NE + 127) / 128;
    const int gridH0 = (NE + 63) / 64;
    const int gridN  = (NN + 127) / 128;
    const int gridW  = (NN * 32) / 256;

    // 1) prep: indices + zero S arrays + ea pre-split
    k_prep<<<2048, 256>>>(eidx, ea, (float*)pS0, (float*)pS1, (float*)pM1);

    // 2) weight split
    const int nsplit = 160 * 176 + 160 * 160 + 160 * 320;
    k_wsplit_all<<<(nsplit + 255) / 256, 256>>>(Wi_w, Wh_w, Wo_w);

    // 3) P = x @ Wi_x^T + Wi_b
    k_mma<<<gridN, 256, MMA_SMEM>>>(x, DIM, DIM, 0, nullptr, 0, 0, 0, 1, NN,
                                    (const unsigned short*)pWih, (const unsigned short*)pWil, 176,
                                    Wi_b, 0, (float*)pP);

    // 4) H0 pass (M=64 tiles): split store + S0 red
    k_h0<<<gridH0, 256, H0_SMEM>>>((const unsigned short*)pEAhi, (const unsigned short*)pEAlo,
                                   (const unsigned short*)pWih, (const unsigned short*)pWil,
                                   (const float*)pP, (const int*)pSrc, (const int*)pDst,
                                   (unsigned short*)pHhi, (unsigned short*)pHlo,
                                   (float*)pS0);

    // 5) T = S0 @ Wh^T + Wh_b
    k_mma<<<gridN, 256, MMA_SMEM>>>((const float*)pS0, DIM, DIM, 0, nullptr, 0, 0, 0, 1, NN,
                                    (const unsigned short*)pWhh, (const unsigned short*)pWhl, DIM,
                                    Wh_b, 0, (float*)pT);

    // 6) iter1
    k_edge<<<gridE, 256, EDGE_SMEM>>>((const unsigned short*)pHhi, (const unsigned short*)pHlo,
                                      (const unsigned short*)pWhh, (const unsigned short*)pWhl,
                                      (const unsigned short*)pHhi, (const unsigned short*)pHlo,
                                      (const float*)pT,
                                      (const int*)pSrc, (const int*)pDst,
                                      (unsigned short*)pGhi, (unsigned short*)pGlo,
                                      (float*)pS1);

    // 7) T = S1 @ Wh^T + Wh_b
    k_mma<<<gridN, 256, MMA_SMEM>>>((const float*)pS1, DIM, DIM, 0, nullptr, 0, 0, 0, 1, NN,
                                    (const unsigned short*)pWhh, (const unsigned short*)pWhl, DIM,
                                    Wh_b, 0, (float*)pT);

    // 8) iter2
    k_edge<<<gridE, 256, EDGE_SMEM>>>((const unsigned short*)pGhi, (const unsigned short*)pGlo,
                                      (const unsigned short*)pWhh, (const unsigned short*)pWhl,
                                      (const unsigned short*)pHhi, (const unsigned short*)pHlo,
                                      (const float*)pT,
                                      (const int*)pSrc, (const int*)pDst,
                                      nullptr, nullptr,
                                      (float*)pM1);

    // 9) where
    k_where<<<gridW, 256>>>((float*)pM1, x);

    // 10) out = relu([x ; M1] @ Wo^T + Wo_b)
    k_mma<<<gridN, 256, MMA_SMEM>>>(x, DIM, DIM, 0, (const float*)pM1, DIM, DIM, DIM, 2, NN,
                                    (const unsigned short*)pWoh, (const unsigned short*)pWol, 2 * DIM,
                                    Wo_b, 1, out);
}

// round 13
// speedup vs baseline: 1.1332x; 1.0501x over previous
#include <cuda_runtime.h>
#include <cstdint>

#define NN 50000
#define NE 500000
#define DIM 160
#define BOND 14
#define WS 88   // k_mma padded k-stride

// ---------------- scratch ----------------
__device__ int   g_src[NE];
__device__ int   g_dst[NE];
__device__ float g_P [NN * DIM];
__device__ unsigned short g_Hhi[NE * DIM], g_Hlo[NE * DIM];
__device__ unsigned short g_Ghi[NE * DIM], g_Glo[NE * DIM];
__device__ unsigned short g_EAhi[NE * 16], g_EAlo[NE * 16];
__device__ float g_S0[NN * DIM];
__device__ float g_S1[NN * DIM];
__device__ float g_M1[NN * DIM];
__device__ float g_T [NN * DIM];
__device__ unsigned short g_Wih[160 * 176], g_Wil[160 * 176];
__device__ unsigned short g_Whh[160 * 160], g_Whl[160 * 160];
__device__ unsigned short g_Woh[160 * 320], g_Wol[160 * 320];
// chunk-major padded W images for bulk copy
__device__ __align__(16) unsigned short g_WhC_hi[5 * 160 * 40], g_WhC_lo[5 * 160 * 40];
__device__ __align__(16) unsigned short g_WiC_hi[160 * 24],     g_WiC_lo[160 * 24];

// ---------------- helpers ----------------
__device__ __forceinline__ uint32_t cvta_s(const void* p) {
    uint32_t r;
    asm("{ .reg .u64 t; cvta.to.shared.u64 t, %1; cvt.u32.u64 %0, t; }" : "=r"(r) : "l"(p));
    return r;
}
__device__ __forceinline__ void ldsm4(uint32_t (&r)[4], uint32_t addr) {
    asm volatile("ldmatrix.sync.aligned.m8n8.x4.shared.b16 {%0,%1,%2,%3}, [%4];"
                 : "=r"(r[0]), "=r"(r[1]), "=r"(r[2]), "=r"(r[3]) : "r"(addr));
}
__device__ __forceinline__ void mma16816(float* c, const uint32_t (&a)[4],
                                         uint32_t b0, uint32_t b1) {
    asm volatile("mma.sync.aligned.m16n8k16.row.col.f32.bf16.bf16.f32 "
                 "{%0,%1,%2,%3},{%4,%5,%6,%7},{%8,%9},{%0,%1,%2,%3};"
                 : "+f"(c[0]), "+f"(c[1]), "+f"(c[2]), "+f"(c[3])
                 : "r"(a[0]), "r"(a[1]), "r"(a[2]), "r"(a[3]), "r"(b0), "r"(b1));
}
__device__ __forceinline__ void split2(float x, float y, uint32_t& hi2, uint32_t& lo2) {
    uint32_t ux = __float_as_uint(x), uy = __float_as_uint(y);
    hi2 = __byte_perm(ux, uy, 0x7632);
    float lx = x - __uint_as_float(ux & 0xffff0000u);
    float ly = y - __uint_as_float(uy & 0xffff0000u);
    asm("cvt.rn.bf16x2.f32 %0, %1, %2;" : "=r"(lo2) : "f"(ly), "f"(lx));
}
__device__ __forceinline__ float2 recon2(uint32_t hi2, uint32_t lo2) {
    float2 r;
    r.x = __uint_as_float(hi2 << 16) + __uint_as_float(lo2 << 16);
    r.y = __uint_as_float(hi2 & 0xffff0000u) + __uint_as_float(lo2 & 0xffff0000u);
    return r;
}
__device__ __forceinline__ void cp16(uint32_t dst, const void* src) {
    asm volatile("cp.async.cg.shared.global [%0], [%1], 16;" :: "r"(dst), "l"(src));
}
__device__ __forceinline__ void bulkcp(uint32_t dst, const void* src, uint32_t bytes,
                                       uint32_t mbar) {
    asm volatile("cp.async.bulk.shared::cta.global.mbarrier::complete_tx::bytes "
                 "[%0], [%1], %2, [%3];"
                 :: "r"(dst), "l"(src), "r"(bytes), "r"(mbar) : "memory");
}
__device__ __forceinline__ void redv4(float* p, float4 v) {
    asm volatile("red.global.add.v4.f32 [%0], {%1,%2,%3,%4};"
                 :: "l"(p), "f"(v.x), "f"(v.y), "f"(v.z), "f"(v.w) : "memory");
}
__device__ __forceinline__ void prefetchL2(const void* p) {
    asm volatile("prefetch.global.L2 [%0];" :: "l"(p));
}

#define MBAR_INIT(addr, cnt) \
    asm volatile("mbarrier.init.shared.b64 [%0], %1;" :: "r"(addr), "r"(cnt) : "memory")
#define MBAR_EXPECT(addr, bytes) \
    asm volatile("mbarrier.arrive.expect_tx.shared.b64 _, [%0], %1;" \
                 :: "r"(addr), "r"(bytes) : "memory")
#define MBAR_WAIT(addr, parity) do {                                              \
    asm volatile(                                                                 \
        "{\n\t.reg .pred P1;\n\t"                                                 \
        "WAIT_LOOP_%=:\n\t"                                                       \
        "mbarrier.try_wait.parity.acquire.cta.shared::cta.b64 P1, [%0], %1, 0x989680;\n\t" \
        "@P1 bra.uni WAIT_DONE_%=;\n\t"                                           \
        "bra.uni WAIT_LOOP_%=;\n\t"                                               \
        "WAIT_DONE_%=:\n\t}"                                                      \
        :: "r"(addr), "r"((uint32_t)(parity)) : "memory");                        \
} while (0)

// ---------------- prep ----------------
__global__ void k_prep(const void* ei, const float* __restrict__ ea,
                       float* S0, float* S1, float* M1) {
    __shared__ int s64;
    if (threadIdx.x < 32) {
        const unsigned long long* p = (const unsigned long long*)ei;
        int bad = 0;
        for (int j = threadIdx.x; j < 1024; j += 32)
            if (p[j] >= (unsigned long long)NN) bad = 1;
        unsigned m = __ballot_sync(0xffffffffu, bad);
        if (threadIdx.x == 0) s64 = (m == 0u);
    }
    __syncthreads();
    const int is64 = s64;
    const int gstride = gridDim.x * blockDim.x;
    int g = blockIdx.x * blockDim.x + threadIdx.x;
    for (int i = g; i < NE; i += gstride) {
        if (is64) {
            const long long* p = (const long long*)ei;
            g_src[i] = (int)p[i];
            g_dst[i] = (int)p[NE + i];
        } else {
            const int* p = (const int*)ei;
            g_src[i] = p[i];
            g_dst[i] = p[NE + i];
        }
    }
    const int nz = NN * DIM / 4;
    float4 z = make_float4(0.f, 0.f, 0.f, 0.f);
    for (int i = g; i < nz; i += gstride) {
        reinterpret_cast<float4*>(S0)[i] = z;
        reinterpret_cast<float4*>(S1)[i] = z;
        reinterpret_cast<float4*>(M1)[i] = z;
    }
    uint32_t* eh = (uint32_t*)g_EAhi;
    uint32_t* el = (uint32_t*)g_EAlo;
    for (int i = g; i < NE * 8; i += gstride) {
        int e = i >> 3, c2 = (i & 7) << 1;
        float2 f = (c2 < BOND) ? *(const float2*)(ea + (size_t)e * BOND + c2)
                               : make_float2(0.f, 0.f);
        uint32_t h2, l2;
        split2(f.x, f.y, h2, l2);
        eh[i] = h2;
        el[i] = l2;
    }
}

// ---------------- weight split (row-major padded, for k_mma) ----------------
__global__ void k_wsplit_all(const float* __restrict__ wi, const float* __restrict__ wh,
                             const float* __restrict__ wo) {
    int i = blockIdx.x * blockDim.x + threadIdx.x;
    const int nWi = 160 * 176, nWh = 160 * 160, nWo = 160 * 320;
    float f;
    unsigned short* hi;
    unsigned short* lo;
    int oi;
    if (i < nWi) {
        int h = i / 176, c = i - h * 176;
        f = (c < 174) ? wi[h * 174 + c] : 0.f;
        hi = g_Wih; lo = g_Wil; oi = i;
    } else if (i < nWi + nWh) {
        oi = i - nWi;
        f = wh[oi];
        hi = g_Whh; lo = g_Whl;
    } else if (i < nWi + nWh + nWo) {
        oi = i - nWi - nWh;
        f = wo[oi];
        hi = g_Woh; lo = g_Wol;
    } else return;
    uint32_t u = __float_as_uint(f);
    hi[oi] = (unsigned short)(u >> 16);
    float lf = f - __uint_as_float(u & 0xffff0000u);
    unsigned short ls;
    asm("cvt.rn.bf16.f32 %0, %1;" : "=h"(ls) : "f"(lf));
    lo[oi] = ls;
}

// ---------------- W chunk images (smem-exact, for bulk copy) ----------------
__global__ void k_wimg(const float* __restrict__ wi, const float* __restrict__ wh) {
    int i = blockIdx.x * blockDim.x + threadIdx.x;
    const int nWh = 5 * 160 * 40, nWi = 160 * 24;
    float f;
    unsigned short *hi, *lo;
    int oi;
    if (i < nWh) {
        int c = i / 6400, rem = i - c * 6400;
        int h = rem / 40, kk = rem - h * 40;
        f = (kk < 32) ? wh[h * 160 + c * 32 + kk] : 0.f;
        hi = g_WhC_hi; lo = g_WhC_lo; oi = i;
    } else if (i < nWh + nWi) {
        int j = i - nWh;
        int h = j / 24, kk = j - h * 24;
        f = (kk < BOND) ? wi[h * 174 + 160 + kk] : 0.f;
        hi = g_WiC_hi; lo = g_WiC_lo; oi = j;
    } else return;
    uint32_t u = __float_as_uint(f);
    hi[oi] = (unsigned short)(u >> 16);
    float lf = f - __uint_as_float(u & 0xffff0000u);
    unsigned short ls;
    asm("cvt.rn.bf16.f32 %0, %1;" : "=h"(ls) : "f"(lf));
    lo[oi] = ls;
}

// ---------------- k_mma smem layout ----------------
#define OFF_WHI 0
#define OFF_WLO (160 * WS * 2)
#define OFF_AHI (2 * 160 * WS * 2)
#define OFF_ALO (2 * 160 * WS * 2 + 128 * WS * 2)
#define MMA_SMEM (2 * 160 * WS * 2 + 2 * 128 * WS * 2)

#define MMA_BODY(aAhi, aAlo, bWhi, bWlo, ksteps, ws)                               \
    for (int ks = 0; ks < (ksteps); ks++) {                                        \
        const uint32_t ko = (uint32_t)ks * 32;                                     \
        uint32_t ah0[4], ah1[4], al0[4], al1[4];                                   \
        ldsm4(ah0, (aAhi) + ko);                                                   \
        ldsm4(ah1, (aAhi) + ko + 16 * (ws) * 2);                                   \
        ldsm4(al0, (aAlo) + ko);                                                   \
        ldsm4(al1, (aAlo) + ko + 16 * (ws) * 2);                                   \
        _Pragma("unroll")                                                          \
        for (int p = 0; p < 5; p++) {                                              \
            const uint32_t bo = ko + (uint32_t)p * (16 * (ws) * 2);                \
            uint32_t bh[4], bl[4];                                                 \
            ldsm4(bh, (bWhi) + bo);                                                \
            ldsm4(bl, (bWlo) + bo);                                                \
            mma16816(acc[2 * p],      ah0, bh[0], bh[1]);                          \
            mma16816(acc[2 * p],      ah0, bl[0], bl[1]);                          \
            mma16816(acc[2 * p],      al0, bh[0], bh[1]);                          \
            mma16816(acc[2 * p + 1],  ah0, bh[2], bh[3]);                          \
            mma16816(acc[2 * p + 1],  ah0, bl[2], bl[3]);                          \
            mma16816(acc[2 * p + 1],  al0, bh[2], bh[3]);                          \
            mma16816(acc[10 + 2 * p],     ah1, bh[0], bh[1]);                      \
            mma16816(acc[10 + 2 * p],     ah1, bl[0], bl[1]);                      \
            mma16816(acc[10 + 2 * p],     al1, bh[0], bh[1]);                      \
            mma16816(acc[10 + 2 * p + 1], ah1, bh[2], bh[3]);                      \
            mma16816(acc[10 + 2 * p + 1], ah1, bl[2], bl[3]);                      \
            mma16816(acc[10 + 2 * p + 1], al1, bh[2], bh[3]);                      \
        }                                                                          \
    }

#define STAGE_ACC(Cs)                                                              \
    {                                                                              \
        const int rf = m0w + (lane >> 2);                                          \
        const int cf = n0w + (lane & 3) * 2;                                       \
        _Pragma("unroll")                                                          \
        for (int mt = 0; mt < 2; mt++)                                             \
            _Pragma("unroll")                                                      \
            for (int half = 0; half < 2; half++) {                                 \
                int rr = rf + mt * 16 + half * 8;                                  \
                _Pragma("unroll")                                                  \
                for (int nt = 0; nt < 10; nt++) {                                  \
                    float* pp = &(Cs)[rr * 164 + cf + nt * 8];                     \
                    pp[0] = acc[mt * 10 + nt][half * 2 + 0];                       \
                    pp[1] = acc[mt * 10 + nt][half * 2 + 1];                       \
                }                                                                  \
            }                                                                      \
    }

// ---------------- generic GEMM (P, T, out) ----------------
__global__ __launch_bounds__(256, 2) void k_mma(
    const float* __restrict__ A0, int lda0, int klen0, int wk0,
    const float* __restrict__ A1, int lda1, int klen1, int wk1,
    int nph, int M,
    const unsigned short* __restrict__ Whi, const unsigned short* __restrict__ Wlo, int ldw,
    const float* __restrict__ bias, int dorelu,
    float* __restrict__ Cout)
{
    extern __shared__ char smem[];
    unsigned short* Whi_s = (unsigned short*)(smem + OFF_WHI);
    unsigned short* Wlo_s = (unsigned short*)(smem + OFF_WLO);
    unsigned short* Ahi_s = (unsigned short*)(smem + OFF_AHI);
    unsigned short* Alo_s = (unsigned short*)(smem + OFF_ALO);
    const uint32_t sbase = cvta_s(smem);

    const int tid = threadIdx.x;
    const int lane = tid & 31, wid = tid >> 5;
    const int warp_m = wid & 3, warp_n = wid >> 2;
    const int m0w = warp_m * 32, n0w = warp_n * 80;
    const int row0 = blockIdx.x * 128;

    const int arow = (lane & 7) + ((lane >> 3) & 1) * 8;
    const int acol = (lane >> 4) * 8;
    const uint32_t aAhi = sbase + OFF_AHI + (uint32_t)((m0w + arow) * WS + acol) * 2;
    const uint32_t aAlo = sbase + OFF_ALO + (uint32_t)((m0w + arow) * WS + acol) * 2;
    const int brow = (lane & 7) + ((lane >> 4) << 3);
    const int bcol = ((lane >> 3) & 1) * 8;
    const uint32_t bWhi = sbase + OFF_WHI + (uint32_t)((n0w + brow) * WS + bcol) * 2;
    const uint32_t bWlo = sbase + OFF_WLO + (uint32_t)((n0w + brow) * WS + bcol) * 2;

    float acc[20][4];
#pragma unroll
    for (int t = 0; t < 20; t++)
#pragma unroll
        for (int j = 0; j < 4; j++) acc[t][j] = 0.f;

    for (int ph = 0; ph < nph; ph++) {
        const float* A = (ph == 0) ? A0 : A1;
        const int lda  = (ph == 0) ? lda0 : lda1;
        const int klen = (ph == 0) ? klen0 : klen1;
        const int wk   = (ph == 0) ? wk0 : wk1;
        const int nch = (klen + 79) / 80;

        for (int c = 0; c < nch; c++) {
            const int k0g = c * 80;
            const int kc = min(80, klen - k0g);
            const bool cpW = (kc == 80) && ((ldw & 7) == 0) && (((wk + k0g) & 7) == 0);
            __syncthreads();

            if (cpW) {
                for (int idx = tid; idx < 160 * 10; idx += 256) {
                    int h = idx / 10, s = idx - h * 10;
                    uint32_t d = (uint32_t)((h * WS + s * 8) * 2);
                    const int gi = h * ldw + wk + k0g + s * 8;
                    cp16(sbase + OFF_WHI + d, Whi + gi);
                    cp16(sbase + OFF_WLO + d, Wlo + gi);
                }
                asm volatile("cp.async.commit_group;");
            } else {
                const int kpad = (kc + 15) & ~15;
                for (int idx = tid; idx < 160 * kpad; idx += 256) {
                    int h = idx / kpad, kk = idx - h * kpad;
                    unsigned short vh = 0, vl = 0;
                    if (kk < kc) {
                        int gi = h * ldw + wk + k0g + kk;
                        vh = Whi[gi]; vl = Wlo[gi];
                    }
                    Whi_s[h * WS + kk] = vh;
                    Wlo_s[h * WS + kk] = vl;
                }
            }

            if (kc == 80 && (lda & 3) == 0) {
                for (int idx = tid; idx < 128 * 20; idx += 256) {
                    int r = idx / 20, q = idx - r * 20;
                    int row = row0 + r;
                    float4 v = make_float4(0.f, 0.f, 0.f, 0.f);
                    if (row < M)
                        v = *reinterpret_cast<const float4*>(A + (size_t)row * lda + k0g + q * 4);
                    uint32_t h2a, l2a, h2b, l2b;
                    split2(v.x, v.y, h2a, l2a);
                    split2(v.z, v.w, h2b, l2b);
                    *(uint2*)&Ahi_s[r * WS + q * 4] = make_uint2(h2a, h2b);
                    *(uint2*)&Alo_s[r * WS + q * 4] = make_uint2(l2a, l2b);
                }
            } else {
                const int kpad = (kc + 15) & ~15;
                for (int idx = tid; idx < 128 * kpad; idx += 256) {
                    int r = idx / kpad, kk = idx - r * kpad;
                    int row = row0 + r;
                    float f = 0.f;
                    if (row < M && kk < kc) f = A[(size_t)row * lda + k0g + kk];
                    uint32_t u = __float_as_uint(f);
                    Ahi_s[r * WS + kk] = (unsigned short)(u >> 16);
                    float lf = f - __uint_as_float(u & 0xffff0000u);
                    unsigned short ls;
                    asm("cvt.rn.bf16.f32 %0, %1;" : "=h"(ls) : "f"(lf));
                    Alo_s[r * WS + kk] = ls;
                }
            }

            if (cpW) asm volatile("cp.async.wait_group 0;");
            __syncthreads();

            const int ksteps = ((kc + 15) & ~15) >> 4;
            MMA_BODY(aAhi, aAlo, bWhi, bWlo, ksteps, WS)
        }
    }

    __syncthreads();
    float* Cs = (float*)smem;
    STAGE_ACC(Cs)
    __syncthreads();

#pragma unroll
    for (int idx = tid; idx < 128 * 20; idx += 256) {
        int r = idx / 20, u = idx - r * 20;
        int row = row0 + r;
        if (row >= M) continue;
        float4 v0 = *reinterpret_cast<float4*>(&Cs[r * 164 + u * 8]);
        float4 v1 = *reinterpret_cast<float4*>(&Cs[r * 164 + u * 8 + 4]);
        if (bias) {
            float4 b0 = __ldg((const float4*)(bias + u * 8));
            float4 b1 = __ldg((const float4*)(bias + u * 8 + 4));
            v0.x += b0.x; v0.y += b0.y; v0.z += b0.z; v0.w += b0.w;
            v1.x += b1.x; v1.y += b1.y; v1.z += b1.z; v1.w += b1.w;
        }
        if (dorelu) {
            v0.x = fmaxf(v0.x, 0.f); v0.y = fmaxf(v0.y, 0.f);
            v0.z = fmaxf(v0.z, 0.f); v0.w = fmaxf(v0.w, 0.f);
            v1.x = fmaxf(v1.x, 0.f); v1.y = fmaxf(v1.y, 0.f);
            v1.z = fmaxf(v1.z, 0.f); v1.w = fmaxf(v1.w, 0.f);
        }
        float4* cp = (float4*)(Cout + (size_t)row * DIM + u * 8);
        cp[0] = v0; cp[1] = v1;
    }
}

// ---------------- H0 kernel: M=64 tiles, 3 CTAs/SM, bulk-copied W ----------------
#define WS3 24
#define O3_WHI 0
#define O3_WLO 7680
#define O3_AHI 15360
#define O3_ALO 18432
#define O3_MBAR (64 * 164 * 4)
#define H0_SMEM (64 * 164 * 4 + 16)

#define MMA16_BODY(aAhi, aAlo, bWhi, bWlo, ksteps, ws)                             \
    for (int ks = 0; ks < (ksteps); ks++) {                                        \
        const uint32_t ko = (uint32_t)ks * 32;                                     \
        uint32_t ah[4], al[4];                                                     \
        ldsm4(ah, (aAhi) + ko);                                                    \
        ldsm4(al, (aAlo) + ko);                                                    \
        _Pragma("unroll")                                                          \
        for (int p = 0; p < 5; p++) {                                              \
            const uint32_t bo = ko + (uint32_t)p * (16 * (ws) * 2);                \
            uint32_t bh[4], bl[4];                                                 \
            ldsm4(bh, (bWhi) + bo);                                                \
            ldsm4(bl, (bWlo) + bo);                                                \
            mma16816(acc[2 * p],     ah, bh[0], bh[1]);                            \
            mma16816(acc[2 * p],     ah, bl[0], bl[1]);                            \
            mma16816(acc[2 * p],     al, bh[0], bh[1]);                            \
            mma16816(acc[2 * p + 1], ah, bh[2], bh[3]);                            \
            mma16816(acc[2 * p + 1], ah, bl[2], bl[3]);                            \
            mma16816(acc[2 * p + 1], al, bh[2], bh[3]);                            \
        }                                                                          \
    }

__global__ __launch_bounds__(256, 3) void k_h0(
    const unsigned short* __restrict__ EAhi, const unsigned short* __restrict__ EAlo,
    const unsigned short* __restrict__ WChi, const unsigned short* __restrict__ WClo,
    const float* __restrict__ P,
    const int* __restrict__ srcIdx, const int* __restrict__ dstIdx,
    unsigned short* __restrict__ OutHi, unsigned short* __restrict__ OutLo,
    float* __restrict__ Sred)
{
    extern __shared__ char smem[];
    const uint32_t sbase = cvta_s(smem);
    const int tid = threadIdx.x;
    const int lane = tid & 31, wid = tid >> 5;
    const int warp_m = wid & 3, warp_n = wid >> 2;
    const int m0w = warp_m * 16, n0w = warp_n * 80;
    const int row0 = blockIdx.x * 64;
    const uint32_t mb = sbase + O3_MBAR;

    if (tid == 0) MBAR_INIT(mb, 1);
    __syncthreads();
    if (tid == 0) {
        MBAR_EXPECT(mb, 15360);
        bulkcp(sbase + O3_WHI, WChi, 7680, mb);
        bulkcp(sbase + O3_WLO, WClo, 7680, mb);
    }

    // prefetch gathered P rows into L2
    for (int idx = tid; idx < 320; idx += 256) {
        int r = idx / 5, s = idx - r * 5;
        int row = row0 + r;
        if (row < NE)
            prefetchL2(P + (size_t)srcIdx[row] * DIM + s * 32);
    }

    // A: 64 rows x 32B (pre-split ea)
    if (tid < 128) {
        int r = tid >> 1, s = tid & 1;
        int row = row0 + r;
        uint32_t d = (uint32_t)(r * (WS3 * 2) + s * 16);
        if (row < NE) {
            const size_t gi = (size_t)row * 16 + s * 8;
            cp16(sbase + O3_AHI + d, EAhi + gi);
            cp16(sbase + O3_ALO + d, EAlo + gi);
        } else {
            uint4 z = make_uint4(0, 0, 0, 0);
            *(uint4*)(smem + O3_AHI + d) = z;
            *(uint4*)(smem + O3_ALO + d) = z;
        }
    }
    asm volatile("cp.async.commit_group;");

    float acc[10][4];
#pragma unroll
    for (int t = 0; t < 10; t++)
#pragma unroll
        for (int j = 0; j < 4; j++) acc[t][j] = 0.f;

    asm volatile("cp.async.wait_group 0;");
    MBAR_WAIT(mb, 0);
    __syncthreads();

    const int arow = (lane & 7) + ((lane >> 3) & 1) * 8;
    const int acol = (lane >> 4) * 8;
    const uint32_t aAhi = sbase + O3_AHI + (uint32_t)((m0w + arow) * WS3 + acol) * 2;
    const uint32_t aAlo = sbase + O3_ALO + (uint32_t)((m0w + arow) * WS3 + acol) * 2;
    const int brow = (lane & 7) + ((lane >> 4) << 3);
    const int bcol = ((lane >> 3) & 1) * 8;
    const uint32_t bWhi = sbase + O3_WHI + (uint32_t)((n0w + brow) * WS3 + bcol) * 2;
    const uint32_t bWlo = sbase + O3_WLO + (uint32_t)((n0w + brow) * WS3 + bcol) * 2;

    MMA16_BODY(aAhi, aAlo, bWhi, bWlo, 1, WS3)

    __syncthreads();
    float* Cs = (float*)smem;
    {
        const int rf = m0w + (lane >> 2);
        const int cf = n0w + (lane & 3) * 2;
#pragma unroll
        for (int half = 0; half < 2; half++) {
            int rr = rf + half * 8;
#pragma unroll
            for (int nt = 0; nt < 10; nt++) {
                float* pp = &Cs[rr * 164 + cf + nt * 8];
                pp[0] = acc[nt][half * 2 + 0];
                pp[1] = acc[nt][half * 2 + 1];
            }
        }
    }
    __syncthreads();

#pragma unroll
    for (int idx = tid; idx < 64 * 20; idx += 256) {
        int r = idx / 20, u = idx - r * 20;
        int row = row0 + r;
        if (row >= NE) continue;
        float4 v0 = *reinterpret_cast<float4*>(&Cs[r * 164 + u * 8]);
        float4 v1 = *reinterpret_cast<float4*>(&Cs[r * 164 + u * 8 + 4]);
        const float* gp = P + (size_t)srcIdx[row] * DIM + u * 8;
        float4 g0 = __ldg((const float4*)gp);
        float4 g1 = __ldg((const float4*)(gp + 4));
        v0.x = fmaxf(v0.x + g0.x, 0.f); v0.y = fmaxf(v0.y + g0.y, 0.f);
        v0.z = fmaxf(v0.z + g0.z, 0.f); v0.w = fmaxf(v0.w + g0.w, 0.f);
        v1.x = fmaxf(v1.x + g1.x, 0.f); v1.y = fmaxf(v1.y + g1.y, 0.f);
        v1.z = fmaxf(v1.z + g1.z, 0.f); v1.w = fmaxf(v1.w + g1.w, 0.f);
        uint4 H, L;
        split2(v0.x, v0.y, H.x, L.x);
        split2(v0.z, v0.w, H.y, L.y);
        split2(v1.x, v1.y, H.z, L.z);
        split2(v1.z, v1.w, H.w, L.w);
        *(uint4*)&OutHi[(size_t)row * DIM + u * 8] = H;
        *(uint4*)&OutLo[(size_t)row * DIM + u * 8] = L;
        float* p = Sred + (size_t)dstIdx[row] * DIM + u * 8;
        redv4(p, v0);
        redv4(p + 4, v1);
    }
}

// ---------------- pipelined edge GEMM, bulk-copied W ----------------
#define WS2 40
#define SSTAGE 46080
#define SOFF_WHI 0
#define SOFF_WLO 12800
#define SOFF_AHI 25600
#define SOFF_ALO 35840
#define E_MBAR (2 * SSTAGE)
#define EDGE_SMEM (2 * SSTAGE + 16)   // 92176 B -> 2 CTAs/SM

__global__ __launch_bounds__(256, 2) void k_edge(
    const unsigned short* __restrict__ Ahi, const unsigned short* __restrict__ Alo,
    const unsigned short* __restrict__ WChi, const unsigned short* __restrict__ WClo,
    const unsigned short* __restrict__ H0hi, const unsigned short* __restrict__ H0lo,
    const float* __restrict__ T,           // includes Wh_b
    const int* __restrict__ srcIdx, const int* __restrict__ dstIdx,
    unsigned short* __restrict__ OutHi, unsigned short* __restrict__ OutLo,
    float* __restrict__ Sred)
{
    extern __shared__ char smem[];
    const uint32_t sbase = cvta_s(smem);

    const int tid = threadIdx.x;
    const int lane = tid & 31, wid = tid >> 5;
    const int warp_m = wid & 3, warp_n = wid >> 2;
    const int m0w = warp_m * 32, n0w = warp_n * 80;
    const int row0 = blockIdx.x * 128;

    if (tid == 0) {
        MBAR_INIT(sbase + E_MBAR, 1);
        MBAR_INIT(sbase + E_MBAR + 8, 1);
    }

    // prefetch gathered T rows into L2
    for (int idx = tid; idx < 640; idx += 256) {
        int r = idx / 5, s = idx - r * 5;
        int row = row0 + r;
        if (row < NE)
            prefetchL2(T + (size_t)srcIdx[row] * DIM + s * 32);
    }
    // prefetch H0 rows (sequential) when distinct from A (edge2)
    if (H0hi != Ahi) {
        const int nb = (min(128, NE - row0)) * (DIM * 2);
        const char* ph = (const char*)(H0hi + (size_t)row0 * DIM);
        const char* pl = (const char*)(H0lo + (size_t)row0 * DIM);
        for (int idx = tid; idx * 128 < nb; idx += 256) {
            prefetchL2(ph + idx * 128);
            prefetchL2(pl + idx * 128);
        }
    }
    __syncthreads();   // mbarrier init visible

    const int arow = (lane & 7) + ((lane >> 3) & 1) * 8;
    const int acol = (lane >> 4) * 8;
    const uint32_t aoff = SOFF_AHI + (uint32_t)((m0w + arow) * WS2 + acol) * 2;
    const int brow = (lane & 7) + ((lane >> 4) << 3);
    const int bcol = ((lane >> 3) & 1) * 8;
    const uint32_t boff = SOFF_WHI + (uint32_t)((n0w + brow) * WS2 + bcol) * 2;

    float acc[20][4];
#pragma unroll
    for (int t = 0; t < 20; t++)
#pragma unroll
        for (int j = 0; j < 4; j++) acc[t][j] = 0.f;

    auto load_chunk = [&](int c) {
        const uint32_t sb = sbase + (uint32_t)(c & 1) * SSTAGE;
        const int k0 = c * 32;
        if (tid == 0) {
            const uint32_t mb = sbase + E_MBAR + (uint32_t)(c & 1) * 8;
            MBAR_EXPECT(mb, 25600);
            bulkcp(sb + SOFF_WHI, WChi + c * 6400, 12800, mb);
            bulkcp(sb + SOFF_WLO, WClo + c * 6400, 12800, mb);
        }
        for (int idx = tid; idx < 512; idx += 256) {
            int r = idx >> 2, s = idx & 3;
            int row = row0 + r;
            uint32_t d = sb + SOFF_AHI + (uint32_t)((r * WS2 + s * 8) * 2);
            if (row < NE) {
                const size_t gi = (size_t)row * DIM + k0 + s * 8;
                cp16(d, Ahi + gi);
                cp16(d + (SOFF_ALO - SOFF_AHI), Alo + gi);
            } else {
                size_t off = (size_t)(c & 1) * SSTAGE + SOFF_AHI + (r * WS2 + s * 8) * 2;
                uint4 z = make_uint4(0, 0, 0, 0);
                *(uint4*)(smem + off) = z;
                *(uint4*)(smem + off + (SOFF_ALO - SOFF_AHI)) = z;
            }
        }
        asm volatile("cp.async.commit_group;");
    };

    load_chunk(0);
    load_chunk(1);

#pragma unroll
    for (int c = 0; c < 5; c++) {
        if (c < 4) asm volatile("cp.async.wait_group 1;");
        else       asm volatile("cp.async.wait_group 0;");
        MBAR_WAIT(sbase + E_MBAR + (uint32_t)(c & 1) * 8, (c >> 1) & 1);
        __syncthreads();
        const uint32_t sb = (uint32_t)(c & 1) * SSTAGE;
        const uint32_t aAhi = sbase + sb + aoff;
        const uint32_t aAlo = aAhi + (SOFF_ALO - SOFF_AHI);
        const uint32_t bWhi = sbase + sb + boff;
        const uint32_t bWlo = bWhi + (SOFF_WLO - SOFF_WHI);
        MMA_BODY(aAhi, aAlo, bWhi, bWlo, 2, WS2)
        if (c < 3) {
            __syncthreads();
            load_chunk(c + 2);
        }
    }

    __syncthreads();
    float* Cs = (float*)smem;
    STAGE_ACC(Cs)
    __syncthreads();

#pragma unroll
    for (int idx = tid; idx < 128 * 20; idx += 256) {
        int r = idx / 20, u = idx - r * 20;
        int row = row0 + r;
        if (row >= NE) continue;
        float4 g0 = *reinterpret_cast<float4*>(&Cs[(r ^ 1) * 164 + u * 8]);
        float4 g1 = *reinterpret_cast<float4*>(&Cs[(r ^ 1) * 164 + u * 8 + 4]);
        uint4 hh = *(const uint4*)&H0hi[(size_t)row * DIM + u * 8];
        uint4 hl = *(const uint4*)&H0lo[(size_t)row * DIM + u * 8];
        float2 ha = recon2(hh.x, hl.x), hb = recon2(hh.y, hl.y);
        float2 hc = recon2(hh.z, hl.z), hd = recon2(hh.w, hl.w);
        const float* tp = T + (size_t)srcIdx[row] * DIM + u * 8;
        float4 t0 = __ldg((const float4*)tp);
        float4 t1 = __ldg((const float4*)(tp + 4));
        float4 v0, v1;
        v0.x = fmaxf(ha.x + t0.x - g0.x, 0.f);
        v0.y = fmaxf(ha.y + t0.y - g0.y, 0.f);
        v0.z = fmaxf(hb.x + t0.z - g0.z, 0.f);
        v0.w = fmaxf(hb.y + t0.w - g0.w, 0.f);
        v1.x = fmaxf(hc.x + t1.x - g1.x, 0.f);
        v1.y = fmaxf(hc.y + t1.y - g1.y, 0.f);
        v1.z = fmaxf(hd.x + t1.z - g1.z, 0.f);
        v1.w = fmaxf(hd.y + t1.w - g1.w, 0.f);
        if (OutHi) {
            uint4 H, L;
            split2(v0.x, v0.y, H.x, L.x);
            split2(v0.z, v0.w, H.y, L.y);
            split2(v1.x, v1.y, H.z, L.z);
            split2(v1.z, v1.w, H.w, L.w);
            *(uint4*)&OutHi[(size_t)row * DIM + u * 8] = H;
            *(uint4*)&OutLo[(size_t)row * DIM + u * 8] = L;
        }
        float* p = Sred + (size_t)dstIdx[row] * DIM + u * 8;
        redv4(p, v0);
        redv4(p + 4, v1);
    }
}

// ---------------- where(rowsum==0, x, M) ----------------
__global__ void k_where(float* __restrict__ M, const float* __restrict__ x)
{
    int gt = blockIdx.x * blockDim.x + threadIdx.x;
    int n = gt >> 5;
    int lane = gt & 31;
    if (n >= NN) return;
    float s = 0.f;
#pragma unroll
    for (int j = 0; j < 5; j++) s += M[n * DIM + lane + j * 32];
#pragma unroll
    for (int o = 16; o; o >>= 1) s += __shfl_xor_sync(0xffffffffu, s, o);
    if (s == 0.f) {
#pragma unroll
        for (int j = 0; j < 5; j++)
            M[n * DIM + lane + j * 32] = x[n * DIM + lane + j * 32];
    }
}

// ---------------- launch ----------------
extern "C" void kernel_launch(void* const* d_in, const int* in_sizes, int n_in,
                              void* d_out, int out_size)
{
    const float* x    = (const float*)d_in[0];
    const float* ea   = (const float*)d_in[1];
    const void*  eidx = d_in[2];
    const float* Wi_w = (const float*)d_in[4];
    const float* Wi_b = (const float*)d_in[5];
    const float* Wh_w = (const float*)d_in[6];
    const float* Wh_b = (const float*)d_in[7];
    const float* Wo_w = (const float*)d_in[8];
    const float* Wo_b = (const float*)d_in[9];
    float* out = (float*)d_out;

    void *pP, *pHhi, *pHlo, *pGhi, *pGlo, *pEAhi, *pEAlo, *pS0, *pS1, *pM1, *pT, *pSrc, *pDst;
    void *pWih, *pWil, *pWhh, *pWhl, *pWoh, *pWol, *pWhCh, *pWhCl, *pWiCh, *pWiCl;
    cudaGetSymbolAddress(&pP,    g_P);
    cudaGetSymbolAddress(&pHhi,  g_Hhi);
    cudaGetSymbolAddress(&pHlo,  g_Hlo);
    cudaGetSymbolAddress(&pGhi,  g_Ghi);
    cudaGetSymbolAddress(&pGlo,  g_Glo);
    cudaGetSymbolAddress(&pEAhi, g_EAhi);
    cudaGetSymbolAddress(&pEAlo, g_EAlo);
    cudaGetSymbolAddress(&pS0,   g_S0);
    cudaGetSymbolAddress(&pS1,   g_S1);
    cudaGetSymbolAddress(&pM1,   g_M1);
    cudaGetSymbolAddress(&pT,    g_T);
    cudaGetSymbolAddress(&pSrc,  g_src);
    cudaGetSymbolAddress(&pDst,  g_dst);
    cudaGetSymbolAddress(&pWih,  g_Wih);
    cudaGetSymbolAddress(&pWil,  g_Wil);
    cudaGetSymbolAddress(&pWhh,  g_Whh);
    cudaGetSymbolAddress(&pWhl,  g_Whl);
    cudaGetSymbolAddress(&pWoh,  g_Woh);
    cudaGetSymbolAddress(&pWol,  g_Wol);
    cudaGetSymbolAddress(&pWhCh, g_WhC_hi);
    cudaGetSymbolAddress(&pWhCl, g_WhC_lo);
    cudaGetSymbolAddress(&pWiCh, g_WiC_hi);
    cudaGetSymbolAddress(&pWiCl, g_WiC_lo);

    cudaFuncSetAttribute(k_mma,  cudaFuncAttributeMaxDynamicSharedMemorySize, MMA_SMEM);
    cudaFuncSetAttribute(k_h0,   cudaFuncAttributeMaxDynamicSharedMemorySize, H0_SMEM);
    cudaFuncSetAttribute(k_edge, cudaFuncAttributeMaxDynamicSharedMemorySize, EDGE_SMEM);

    static cudaStream_t s2 = nullptr;
    static cudaEvent_t evF = nullptr, evJ = nullptr;
    if (!s2) {
        cudaStreamCreateWithFlags(&s2, cudaStreamNonBlocking);
        cudaEventCreateWithFlags(&evF, cudaEventDisableTiming);
        cudaEventCreateWithFlags(&evJ, cudaEventDisableTiming);
    }

    const int gridE  = (NE + 127) / 128;
    const int gridH0 = (NE + 63) / 64;
    const int gridN  = (NN + 127) / 128;
    const int gridW  = (NN * 32) / 256;

    // fork: weights + P on s2, prep on default
    cudaEventRecord(evF, 0);
    cudaStreamWaitEvent(s2, evF, 0);

    const int nsplit = 160 * 176 + 160 * 160 + 160 * 320;
    k_wsplit_all<<<(nsplit + 255) / 256, 256, 0, s2>>>(Wi_w, Wh_w, Wo_w);
    const int nimg = 5 * 160 * 40 + 160 * 24;
    k_wimg<<<(nimg + 255) / 256, 256, 0, s2>>>(Wi_w, Wh_w);
    k_mma<<<gridN, 256, MMA_SMEM, s2>>>(x, DIM, DIM, 0, nullptr, 0, 0, 0, 1, NN,
                                        (const unsigned short*)pWih, (const unsigned short*)pWil, 176,
                                        Wi_b, 0, (float*)pP);
    cudaEventRecord(evJ, s2);

    k_prep<<<2048, 256>>>(eidx, ea, (float*)pS0, (float*)pS1, (float*)pM1);
    cudaStreamWaitEvent(0, evJ, 0);

    // H0 pass
    k_h0<<<gridH0, 256, H0_SMEM>>>((const unsigned short*)pEAhi, (const unsigned short*)pEAlo,
                                   (const unsigned short*)pWiCh, (const unsigned short*)pWiCl,
                                   (const float*)pP, (const int*)pSrc, (const int*)pDst,
                                   (unsigned short*)pHhi, (unsigned short*)pHlo,
                                   (float*)pS0);

    // T = S0 @ Wh^T + Wh_b
    k_mma<<<gridN, 256, MMA_SMEM>>>((const float*)pS0, DIM, DIM, 0, nullptr, 0, 0, 0, 1, NN,
                                    (const unsigned short*)pWhh, (const unsigned short*)pWhl, DIM,
                                    Wh_b, 0, (float*)pT);

    // iter1
    k_edge<<<gridE, 256, EDGE_SMEM>>>((const unsigned short*)pHhi, (const unsigned short*)pHlo,
                                      (const unsigned short*)pWhCh, (const unsigned short*)pWhCl,
                                      (const unsigned short*)pHhi, (const unsigned short*)pHlo,
                                      (const float*)pT,
                                      (const int*)pSrc, (const int*)pDst,
                                      (unsigned short*)pGhi, (unsigned short*)pGlo,
                                      (float*)pS1);

    // T = S1 @ Wh^T + Wh_b
    k_mma<<<gridN, 256, MMA_SMEM>>>((const float*)pS1, DIM, DIM, 0, nullptr, 0, 0, 0, 1, NN,
                                    (const unsigned short*)pWhh, (const unsigned short*)pWhl, DIM,
                                    Wh_b, 0, (float*)pT);

    // iter2
    k_edge<<<gridE, 256, EDGE_SMEM>>>((const unsigned short*)pGhi, (const unsigned short*)pGlo,
                                      (const unsigned short*)pWhCh, (const unsigned short*)pWhCl,
                                      (const unsigned short*)pHhi, (const unsigned short*)pHlo,
                                      (const float*)pT,
                                      (const int*)pSrc, (const int*)pDst,
                                      nullptr, nullptr,
                                      (float*)pM1);

    // where
    k_where<<<gridW, 256>>>((float*)pM1, x);

    // out = relu([x ; M1] @ Wo^T + Wo_b)
    k_mma<<<gridN, 256, MMA_SMEM>>>(x, DIM, DIM, 0, (const float*)pM1, DIM, DIM, DIM, 2, NN,
                                    (const unsigned short*)pWoh, (const unsigned short*)pWol, 2 * DIM,
                                    Wo_b, 1, out);
}

// round 14
// speedup vs baseline: 1.1347x; 1.0013x over previous
#include <cuda_runtime.h>
#include <cstdint>

#define NN 50000
#define NE 500000
#define DIM 160
#define BOND 14
#define WS 88   // k_mma padded k-stride

// ---------------- scratch ----------------
__device__ int   g_src[NE];
__device__ int   g_dst[NE];
__device__ float g_P [NN * DIM];
// H tensors in CHUNK-MAJOR split-bf16: [5][NE][32] (+ tail pad for bulk overrun)
__device__ unsigned short g_Hhi[NE * DIM + 8192], g_Hlo[NE * DIM + 8192];
__device__ unsigned short g_Ghi[NE * DIM + 8192], g_Glo[NE * DIM + 8192];
__device__ unsigned short g_EAhi[NE * 16 + 1024], g_EAlo[NE * 16 + 1024];
__device__ float g_S0[NN * DIM];
__device__ float g_S1[NN * DIM];
__device__ float g_M1[NN * DIM];
__device__ float g_T [NN * DIM];
__device__ unsigned short g_Wih[160 * 176], g_Wil[160 * 176];
__device__ unsigned short g_Whh[160 * 160], g_Whl[160 * 160];
__device__ unsigned short g_Woh[160 * 320], g_Wol[160 * 320];
__device__ __align__(16) unsigned short g_WhC_hi[5 * 160 * 40], g_WhC_lo[5 * 160 * 40];
__device__ __align__(16) unsigned short g_WiC_hi[160 * 24],     g_WiC_lo[160 * 24];

// ---------------- helpers ----------------
__device__ __forceinline__ uint32_t cvta_s(const void* p) {
    uint32_t r;
    asm("{ .reg .u64 t; cvta.to.shared.u64 t, %1; cvt.u32.u64 %0, t; }" : "=r"(r) : "l"(p));
    return r;
}
__device__ __forceinline__ void ldsm4(uint32_t (&r)[4], uint32_t addr) {
    asm volatile("ldmatrix.sync.aligned.m8n8.x4.shared.b16 {%0,%1,%2,%3}, [%4];"
                 : "=r"(r[0]), "=r"(r[1]), "=r"(r[2]), "=r"(r[3]) : "r"(addr));
}
__device__ __forceinline__ void mma16816(float* c, const uint32_t (&a)[4],
                                         uint32_t b0, uint32_t b1) {
    asm volatile("mma.sync.aligned.m16n8k16.row.col.f32.bf16.bf16.f32 "
                 "{%0,%1,%2,%3},{%4,%5,%6,%7},{%8,%9},{%0,%1,%2,%3};"
                 : "+f"(c[0]), "+f"(c[1]), "+f"(c[2]), "+f"(c[3])
                 : "r"(a[0]), "r"(a[1]), "r"(a[2]), "r"(a[3]), "r"(b0), "r"(b1));
}
__device__ __forceinline__ void split2(float x, float y, uint32_t& hi2, uint32_t& lo2) {
    uint32_t ux = __float_as_uint(x), uy = __float_as_uint(y);
    hi2 = __byte_perm(ux, uy, 0x7632);
    float lx = x - __uint_as_float(ux & 0xffff0000u);
    float ly = y - __uint_as_float(uy & 0xffff0000u);
    asm("cvt.rn.bf16x2.f32 %0, %1, %2;" : "=r"(lo2) : "f"(ly), "f"(lx));
}
__device__ __forceinline__ float2 recon2(uint32_t hi2, uint32_t lo2) {
    float2 r;
    r.x = __uint_as_float(hi2 << 16) + __uint_as_float(lo2 << 16);
    r.y = __uint_as_float(hi2 & 0xffff0000u) + __uint_as_float(lo2 & 0xffff0000u);
    return r;
}
__device__ __forceinline__ void cp16(uint32_t dst, const void* src) {
    asm volatile("cp.async.cg.shared.global [%0], [%1], 16;" :: "r"(dst), "l"(src));
}
__device__ __forceinline__ void bulkcp(uint32_t dst, const void* src, uint32_t bytes,
                                       uint32_t mbar) {
    asm volatile("cp.async.bulk.shared::cta.global.mbarrier::complete_tx::bytes "
                 "[%0], [%1], %2, [%3];"
                 :: "r"(dst), "l"(src), "r"(bytes), "r"(mbar) : "memory");
}
__device__ __forceinline__ void redv4(float* p, float4 v) {
    asm volatile("red.global.add.v4.f32 [%0], {%1,%2,%3,%4};"
                 :: "l"(p), "f"(v.x), "f"(v.y), "f"(v.z), "f"(v.w) : "memory");
}
__device__ __forceinline__ void prefetchL2(const void* p) {
    asm volatile("prefetch.global.L2 [%0];" :: "l"(p));
}

#define MBAR_INIT(addr, cnt) \
    asm volatile("mbarrier.init.shared.b64 [%0], %1;" :: "r"(addr), "r"(cnt) : "memory")
#define MBAR_EXPECT(addr, bytes) \
    asm volatile("mbarrier.arrive.expect_tx.shared.b64 _, [%0], %1;" \
                 :: "r"(addr), "r"(bytes) : "memory")
#define MBAR_WAIT(addr, parity) do {                                              \
    asm volatile(                                                                 \
        "{\n\t.reg .pred P1;\n\t"                                                 \
        "WAIT_LOOP_%=:\n\t"                                                       \
        "mbarrier.try_wait.parity.acquire.cta.shared::cta.b64 P1, [%0], %1, 0x989680;\n\t" \
        "@P1 bra.uni WAIT_DONE_%=;\n\t"                                           \
        "bra.uni WAIT_LOOP_%=;\n\t"                                               \
        "WAIT_DONE_%=:\n\t}"                                                      \
        :: "r"(addr), "r"((uint32_t)(parity)) : "memory");                        \
} while (0)

// ---------------- prep ----------------
__global__ void k_prep(const void* ei, const float* __restrict__ ea,
                       float* S0, float* S1, float* M1) {
    __shared__ int s64;
    if (threadIdx.x < 32) {
        const unsigned long long* p = (const unsigned long long*)ei;
        int bad = 0;
        for (int j = threadIdx.x; j < 1024; j += 32)
            if (p[j] >= (unsigned long long)NN) bad = 1;
        unsigned m = __ballot_sync(0xffffffffu, bad);
        if (threadIdx.x == 0) s64 = (m == 0u);
    }
    __syncthreads();
    const int is64 = s64;
    const int gstride = gridDim.x * blockDim.x;
    int g = blockIdx.x * blockDim.x + threadIdx.x;
    for (int i = g; i < NE; i += gstride) {
        if (is64) {
            const long long* p = (const long long*)ei;
            g_src[i] = (int)p[i];
            g_dst[i] = (int)p[NE + i];
        } else {
            const int* p = (const int*)ei;
            g_src[i] = p[i];
            g_dst[i] = p[NE + i];
        }
    }
    const int nz = NN * DIM / 4;
    float4 z = make_float4(0.f, 0.f, 0.f, 0.f);
    for (int i = g; i < nz; i += gstride) {
        reinterpret_cast<float4*>(S0)[i] = z;
        reinterpret_cast<float4*>(S1)[i] = z;
        reinterpret_cast<float4*>(M1)[i] = z;
    }
    uint32_t* eh = (uint32_t*)g_EAhi;
    uint32_t* el = (uint32_t*)g_EAlo;
    for (int i = g; i < NE * 8; i += gstride) {
        int e = i >> 3, c2 = (i & 7) << 1;
        float2 f = (c2 < BOND) ? *(const float2*)(ea + (size_t)e * BOND + c2)
                               : make_float2(0.f, 0.f);
        uint32_t h2, l2;
        split2(f.x, f.y, h2, l2);
        eh[i] = h2;
        el[i] = l2;
    }
}

// ---------------- weight split (row-major padded, for k_mma) ----------------
__global__ void k_wsplit_all(const float* __restrict__ wi, const float* __restrict__ wh,
                             const float* __restrict__ wo) {
    int i = blockIdx.x * blockDim.x + threadIdx.x;
    const int nWi = 160 * 176, nWh = 160 * 160, nWo = 160 * 320;
    float f;
    unsigned short* hi;
    unsigned short* lo;
    int oi;
    if (i < nWi) {
        int h = i / 176, c = i - h * 176;
        f = (c < 174) ? wi[h * 174 + c] : 0.f;
        hi = g_Wih; lo = g_Wil; oi = i;
    } else if (i < nWi + nWh) {
        oi = i - nWi;
        f = wh[oi];
        hi = g_Whh; lo = g_Whl;
    } else if (i < nWi + nWh + nWo) {
        oi = i - nWi - nWh;
        f = wo[oi];
        hi = g_Woh; lo = g_Wol;
    } else return;
    uint32_t u = __float_as_uint(f);
    hi[oi] = (unsigned short)(u >> 16);
    float lf = f - __uint_as_float(u & 0xffff0000u);
    unsigned short ls;
    asm("cvt.rn.bf16.f32 %0, %1;" : "=h"(ls) : "f"(lf));
    lo[oi] = ls;
}

// ---------------- W chunk images ----------------
__global__ void k_wimg(const float* __restrict__ wi, const float* __restrict__ wh) {
    int i = blockIdx.x * blockDim.x + threadIdx.x;
    const int nWh = 5 * 160 * 40, nWi = 160 * 24;
    float f;
    unsigned short *hi, *lo;
    int oi;
    if (i < nWh) {
        int c = i / 6400, rem = i - c * 6400;
        int h = rem / 40, kk = rem - h * 40;
        f = (kk < 32) ? wh[h * 160 + c * 32 + kk] : 0.f;
        hi = g_WhC_hi; lo = g_WhC_lo; oi = i;
    } else if (i < nWh + nWi) {
        int j = i - nWh;
        int h = j / 24, kk = j - h * 24;
        f = (kk < BOND) ? wi[h * 174 + 160 + kk] : 0.f;
        hi = g_WiC_hi; lo = g_WiC_lo; oi = j;
    } else return;
    uint32_t u = __float_as_uint(f);
    hi[oi] = (unsigned short)(u >> 16);
    float lf = f - __uint_as_float(u & 0xffff0000u);
    unsigned short ls;
    asm("cvt.rn.bf16.f32 %0, %1;" : "=h"(ls) : "f"(lf));
    lo[oi] = ls;
}

// ---------------- k_mma smem layout ----------------
#define OFF_WHI 0
#define OFF_WLO (160 * WS * 2)
#define OFF_AHI (2 * 160 * WS * 2)
#define OFF_ALO (2 * 160 * WS * 2 + 128 * WS * 2)
#define MMA_SMEM (2 * 160 * WS * 2 + 2 * 128 * WS * 2)

#define MMA_BODY(aAhi, aAlo, bWhi, bWlo, ksteps, wsA, wsW)                         \
    for (int ks = 0; ks < (ksteps); ks++) {                                        \
        const uint32_t ko = (uint32_t)ks * 32;                                     \
        uint32_t ah0[4], ah1[4], al0[4], al1[4];                                   \
        ldsm4(ah0, (aAhi) + ko);                                                   \
        ldsm4(ah1, (aAhi) + ko + 16 * (wsA) * 2);                                  \
        ldsm4(al0, (aAlo) + ko);                                                   \
        ldsm4(al1, (aAlo) + ko + 16 * (wsA) * 2);                                  \
        _Pragma("unroll")                                                          \
        for (int p = 0; p < 5; p++) {                                              \
            const uint32_t bo = ko + (uint32_t)p * (16 * (wsW) * 2);               \
            uint32_t bh[4], bl[4];                                                 \
            ldsm4(bh, (bWhi) + bo);                                                \
            ldsm4(bl, (bWlo) + bo);                                                \
            mma16816(acc[2 * p],      ah0, bh[0], bh[1]);                          \
            mma16816(acc[2 * p],      ah0, bl[0], bl[1]);                          \
            mma16816(acc[2 * p],      al0, bh[0], bh[1]);                          \
            mma16816(acc[2 * p + 1],  ah0, bh[2], bh[3]);                          \
            mma16816(acc[2 * p + 1],  ah0, bl[2], bl[3]);                          \
            mma16816(acc[2 * p + 1],  al0, bh[2], bh[3]);                          \
            mma16816(acc[10 + 2 * p],     ah1, bh[0], bh[1]);                      \
            mma16816(acc[10 + 2 * p],     ah1, bl[0], bl[1]);                      \
            mma16816(acc[10 + 2 * p],     al1, bh[0], bh[1]);                      \
            mma16816(acc[10 + 2 * p + 1], ah1, bh[2], bh[3]);                      \
            mma16816(acc[10 + 2 * p + 1], ah1, bl[2], bl[3]);                      \
            mma16816(acc[10 + 2 * p + 1], al1, bh[2], bh[3]);                      \
        }                                                                          \
    }

#define STAGE_ACC(Cs)                                                              \
    {                                                                              \
        const int rf = m0w + (lane >> 2);                                          \
        const int cf = n0w + (lane & 3) * 2;                                       \
        _Pragma("unroll")                                                          \
        for (int mt = 0; mt < 2; mt++)                                             \
            _Pragma("unroll")                                                      \
            for (int half = 0; half < 2; half++) {                                 \
                int rr = rf + mt * 16 + half * 8;                                  \
                _Pragma("unroll")                                                  \
                for (int nt = 0; nt < 10; nt++) {                                  \
                    float* pp = &(Cs)[rr * 164 + cf + nt * 8];                     \
                    pp[0] = acc[mt * 10 + nt][half * 2 + 0];                       \
                    pp[1] = acc[mt * 10 + nt][half * 2 + 1];                       \
                }                                                                  \
            }                                                                      \
    }

// ---------------- generic GEMM (P, T, out) ----------------
__global__ __launch_bounds__(256, 2) void k_mma(
    const float* __restrict__ A0, int lda0, int klen0, int wk0,
    const float* __restrict__ A1, int lda1, int klen1, int wk1,
    int nph, int M,
    const unsigned short* __restrict__ Whi, const unsigned short* __restrict__ Wlo, int ldw,
    const float* __restrict__ bias, int dorelu,
    float* __restrict__ Cout)
{
    extern __shared__ char smem[];
    unsigned short* Whi_s = (unsigned short*)(smem + OFF_WHI);
    unsigned short* Wlo_s = (unsigned short*)(smem + OFF_WLO);
    unsigned short* Ahi_s = (unsigned short*)(smem + OFF_AHI);
    unsigned short* Alo_s = (unsigned short*)(smem + OFF_ALO);
    const uint32_t sbase = cvta_s(smem);

    const int tid = threadIdx.x;
    const int lane = tid & 31, wid = tid >> 5;
    const int warp_m = wid & 3, warp_n = wid >> 2;
    const int m0w = warp_m * 32, n0w = warp_n * 80;
    const int row0 = blockIdx.x * 128;

    const int arow = (lane & 7) + ((lane >> 3) & 1) * 8;
    const int acol = (lane >> 4) * 8;
    const uint32_t aAhi = sbase + OFF_AHI + (uint32_t)((m0w + arow) * WS + acol) * 2;
    const uint32_t aAlo = sbase + OFF_ALO + (uint32_t)((m0w + arow) * WS + acol) * 2;
    const int brow = (lane & 7) + ((lane >> 4) << 3);
    const int bcol = ((lane >> 3) & 1) * 8;
    const uint32_t bWhi = sbase + OFF_WHI + (uint32_t)((n0w + brow) * WS + bcol) * 2;
    const uint32_t bWlo = sbase + OFF_WLO + (uint32_t)((n0w + brow) * WS + bcol) * 2;

    float acc[20][4];
#pragma unroll
    for (int t = 0; t < 20; t++)
#pragma unroll
        for (int j = 0; j < 4; j++) acc[t][j] = 0.f;

    for (int ph = 0; ph < nph; ph++) {
        const float* A = (ph == 0) ? A0 : A1;
        const int lda  = (ph == 0) ? lda0 : lda1;
        const int klen = (ph == 0) ? klen0 : klen1;
        const int wk   = (ph == 0) ? wk0 : wk1;
        const int nch = (klen + 79) / 80;

        for (int c = 0; c < nch; c++) {
            const int k0g = c * 80;
            const int kc = min(80, klen - k0g);
            const bool cpW = (kc == 80) && ((ldw & 7) == 0) && (((wk + k0g) & 7) == 0);
            __syncthreads();

            if (cpW) {
                for (int idx = tid; idx < 160 * 10; idx += 256) {
                    int h = idx / 10, s = idx - h * 10;
                    uint32_t d = (uint32_t)((h * WS + s * 8) * 2);
                    const int gi = h * ldw + wk + k0g + s * 8;
                    cp16(sbase + OFF_WHI + d, Whi + gi);
                    cp16(sbase + OFF_WLO + d, Wlo + gi);
                }
                asm volatile("cp.async.commit_group;");
            } else {
                const int kpad = (kc + 15) & ~15;
                for (int idx = tid; idx < 160 * kpad; idx += 256) {
                    int h = idx / kpad, kk = idx - h * kpad;
                    unsigned short vh = 0, vl = 0;
                    if (kk < kc) {
                        int gi = h * ldw + wk + k0g + kk;
                        vh = Whi[gi]; vl = Wlo[gi];
                    }
                    Whi_s[h * WS + kk] = vh;
                    Wlo_s[h * WS + kk] = vl;
                }
            }

            if (kc == 80 && (lda & 3) == 0) {
                for (int idx = tid; idx < 128 * 20; idx += 256) {
                    int r = idx / 20, q = idx - r * 20;
                    int row = row0 + r;
                    float4 v = make_float4(0.f, 0.f, 0.f, 0.f);
                    if (row < M)
                        v = *reinterpret_cast<const float4*>(A + (size_t)row * lda + k0g + q * 4);
                    uint32_t h2a, l2a, h2b, l2b;
                    split2(v.x, v.y, h2a, l2a);
                    split2(v.z, v.w, h2b, l2b);
                    *(uint2*)&Ahi_s[r * WS + q * 4] = make_uint2(h2a, h2b);
                    *(uint2*)&Alo_s[r * WS + q * 4] = make_uint2(l2a, l2b);
                }
            } else {
                const int kpad = (kc + 15) & ~15;
                for (int idx = tid; idx < 128 * kpad; idx += 256) {
                    int r = idx / kpad, kk = idx - r * kpad;
                    int row = row0 + r;
                    float f = 0.f;
                    if (row < M && kk < kc) f = A[(size_t)row * lda + k0g + kk];
                    uint32_t u = __float_as_uint(f);
                    Ahi_s[r * WS + kk] = (unsigned short)(u >> 16);
                    float lf = f - __uint_as_float(u & 0xffff0000u);
                    unsigned short ls;
                    asm("cvt.rn.bf16.f32 %0, %1;" : "=h"(ls) : "f"(lf));
                    Alo_s[r * WS + kk] = ls;
                }
            }

            if (cpW) asm volatile("cp.async.wait_group 0;");
            __syncthreads();

            const int ksteps = ((kc + 15) & ~15) >> 4;
            MMA_BODY(aAhi, aAlo, bWhi, bWlo, ksteps, WS, WS)
        }
    }

    __syncthreads();
    float* Cs = (float*)smem;
    STAGE_ACC(Cs)
    __syncthreads();

#pragma unroll
    for (int idx = tid; idx < 128 * 20; idx += 256) {
        int r = idx / 20, u = idx - r * 20;
        int row = row0 + r;
        if (row >= M) continue;
        float4 v0 = *reinterpret_cast<float4*>(&Cs[r * 164 + u * 8]);
        float4 v1 = *reinterpret_cast<float4*>(&Cs[r * 164 + u * 8 + 4]);
        if (bias) {
            float4 b0 = __ldg((const float4*)(bias + u * 8));
            float4 b1 = __ldg((const float4*)(bias + u * 8 + 4));
            v0.x += b0.x; v0.y += b0.y; v0.z += b0.z; v0.w += b0.w;
            v1.x += b1.x; v1.y += b1.y; v1.z += b1.z; v1.w += b1.w;
        }
        if (dorelu) {
            v0.x = fmaxf(v0.x, 0.f); v0.y = fmaxf(v0.y, 0.f);
            v0.z = fmaxf(v0.z, 0.f); v0.w = fmaxf(v0.w, 0.f);
            v1.x = fmaxf(v1.x, 0.f); v1.y = fmaxf(v1.y, 0.f);
            v1.z = fmaxf(v1.z, 0.f); v1.w = fmaxf(v1.w, 0.f);
        }
        float4* cp = (float4*)(Cout + (size_t)row * DIM + u * 8);
        cp[0] = v0; cp[1] = v1;
    }
}

// ---------------- H0 kernel: M=64, 3 CTAs/SM, fully bulk-copied operands ----------------
#define WS3A 16
#define WS3W 24
#define O3_WHI 0
#define O3_WLO 7680
#define O3_AHI 15360
#define O3_ALO 17408
#define O3_MBAR (64 * 164 * 4)
#define H0_SMEM (64 * 164 * 4 + 16)

#define MMA16_BODY(aAhi, aAlo, bWhi, bWlo, ksteps, wsW)                            \
    for (int ks = 0; ks < (ksteps); ks++) {                                        \
        const uint32_t ko = (uint32_t)ks * 32;                                     \
        uint32_t ah[4], al[4];                                                     \
        ldsm4(ah, (aAhi) + ko);                                                    \
        ldsm4(al, (aAlo) + ko);                                                    \
        _Pragma("unroll")                                                          \
        for (int p = 0; p < 5; p++) {                                              \
            const uint32_t bo = ko + (uint32_t)p * (16 * (wsW) * 2);               \
            uint32_t bh[4], bl[4];                                                 \
            ldsm4(bh, (bWhi) + bo);                                                \
            ldsm4(bl, (bWlo) + bo);                                                \
            mma16816(acc[2 * p],     ah, bh[0], bh[1]);                            \
            mma16816(acc[2 * p],     ah, bl[0], bl[1]);                            \
            mma16816(acc[2 * p],     al, bh[0], bh[1]);                            \
            mma16816(acc[2 * p + 1], ah, bh[2], bh[3]);                            \
            mma16816(acc[2 * p + 1], ah, bl[2], bl[3]);                            \
            mma16816(acc[2 * p + 1], al, bh[2], bh[3]);                            \
        }                                                                          \
    }

__global__ __launch_bounds__(256, 3) void k_h0(
    const unsigned short* __restrict__ EAhi, const unsigned short* __restrict__ EAlo,
    const unsigned short* __restrict__ WChi, const unsigned short* __restrict__ WClo,
    const float* __restrict__ P,
    const int* __restrict__ srcIdx, const int* __restrict__ dstIdx,
    unsigned short* __restrict__ OutHi, unsigned short* __restrict__ OutLo,
    float* __restrict__ Sred)
{
    extern __shared__ char smem[];
    const uint32_t sbase = cvta_s(smem);
    const int tid = threadIdx.x;
    const int lane = tid & 31, wid = tid >> 5;
    const int warp_m = wid & 3, warp_n = wid >> 2;
    const int m0w = warp_m * 16, n0w = warp_n * 80;
    const int row0 = blockIdx.x * 64;
    const uint32_t mb = sbase + O3_MBAR;

    if (tid == 0) MBAR_INIT(mb, 1);
    __syncthreads();
    if (tid == 0) {
        MBAR_EXPECT(mb, 19456);
        bulkcp(sbase + O3_WHI, WChi, 7680, mb);
        bulkcp(sbase + O3_WLO, WClo, 7680, mb);
        bulkcp(sbase + O3_AHI, EAhi + (size_t)row0 * 16, 2048, mb);
        bulkcp(sbase + O3_ALO, EAlo + (size_t)row0 * 16, 2048, mb);
    }

    // prefetch gathered P rows into L2
    for (int idx = tid; idx < 320; idx += 256) {
        int r = idx / 5, s = idx - r * 5;
        int row = row0 + r;
        if (row < NE)
            prefetchL2(P + (size_t)srcIdx[row] * DIM + s * 32);
    }

    float acc[10][4];
#pragma unroll
    for (int t = 0; t < 10; t++)
#pragma unroll
        for (int j = 0; j < 4; j++) acc[t][j] = 0.f;

    MBAR_WAIT(mb, 0);
    __syncthreads();

    const int arow = (lane & 7) + ((lane >> 3) & 1) * 8;
    const int acol = (lane >> 4) * 8;
    const uint32_t aAhi = sbase + O3_AHI + (uint32_t)((m0w + arow) * WS3A + acol) * 2;
    const uint32_t aAlo = sbase + O3_ALO + (uint32_t)((m0w + arow) * WS3A + acol) * 2;
    const int brow = (lane & 7) + ((lane >> 4) << 3);
    const int bcol = ((lane >> 3) & 1) * 8;
    const uint32_t bWhi = sbase + O3_WHI + (uint32_t)((n0w + brow) * WS3W + bcol) * 2;
    const uint32_t bWlo = sbase + O3_WLO + (uint32_t)((n0w + brow) * WS3W + bcol) * 2;

    MMA16_BODY(aAhi, aAlo, bWhi, bWlo, 1, WS3W)

    __syncthreads();
    float* Cs = (float*)smem;
    {
        const int rf = m0w + (lane >> 2);
        const int cf = n0w + (lane & 3) * 2;
#pragma unroll
        for (int half = 0; half < 2; half++) {
            int rr = rf + half * 8;
#pragma unroll
            for (int nt = 0; nt < 10; nt++) {
                float* pp = &Cs[rr * 164 + cf + nt * 8];
                pp[0] = acc[nt][half * 2 + 0];
                pp[1] = acc[nt][half * 2 + 1];
            }
        }
    }
    __syncthreads();

#pragma unroll
    for (int idx = tid; idx < 64 * 20; idx += 256) {
        int r = idx / 20, u = idx - r * 20;
        int row = row0 + r;
        if (row >= NE) continue;
        float4 v0 = *reinterpret_cast<float4*>(&Cs[r * 164 + u * 8]);
        float4 v1 = *reinterpret_cast<float4*>(&Cs[r * 164 + u * 8 + 4]);
        const float* gp = P + (size_t)srcIdx[row] * DIM + u * 8;
        float4 g0 = __ldg((const float4*)gp);
        float4 g1 = __ldg((const float4*)(gp + 4));
        v0.x = fmaxf(v0.x + g0.x, 0.f); v0.y = fmaxf(v0.y + g0.y, 0.f);
        v0.z = fmaxf(v0.z + g0.z, 0.f); v0.w = fmaxf(v0.w + g0.w, 0.f);
        v1.x = fmaxf(v1.x + g1.x, 0.f); v1.y = fmaxf(v1.y + g1.y, 0.f);
        v1.z = fmaxf(v1.z + g1.z, 0.f); v1.w = fmaxf(v1.w + g1.w, 0.f);
        uint4 H, L;
        split2(v0.x, v0.y, H.x, L.x);
        split2(v0.z, v0.w, H.y, L.y);
        split2(v1.x, v1.y, H.z, L.z);
        split2(v1.z, v1.w, H.w, L.w);
        // chunk-major store: col block u -> chunk u>>2, offset (u&3)*8
        const size_t cb = (size_t)(u >> 2) * (NE * 32) + (size_t)row * 32 + (u & 3) * 8;
        *(uint4*)&OutHi[cb] = H;
        *(uint4*)&OutLo[cb] = L;
        float* p = Sred + (size_t)dstIdx[row] * DIM + u * 8;
        redv4(p, v0);
        redv4(p + 4, v1);
    }
}

// ---------------- pipelined edge GEMM, fully bulk-copied operands ----------------
#define WS2A 32
#define WS2W 40
#define SOFF_WHI 0
#define SOFF_WLO 12800
#define SOFF_AHI 25600
#define SOFF_ALO 33792
#define SSTAGE 41984
#define E_MBAR (2 * SSTAGE)
#define EDGE_SMEM (2 * SSTAGE + 16)   // 83984 B -> 2 CTAs/SM

__global__ __launch_bounds__(256, 2) void k_edge(
    const unsigned short* __restrict__ Ahi, const unsigned short* __restrict__ Alo,
    const unsigned short* __restrict__ WChi, const unsigned short* __restrict__ WClo,
    const unsigned short* __restrict__ H0hi, const unsigned short* __restrict__ H0lo,
    const float* __restrict__ T,           // includes Wh_b
    const int* __restrict__ srcIdx, const int* __restrict__ dstIdx,
    unsigned short* __restrict__ OutHi, unsigned short* __restrict__ OutLo,
    float* __restrict__ Sred)
{
    extern __shared__ char smem[];
    const uint32_t sbase = cvta_s(smem);

    const int tid = threadIdx.x;
    const int lane = tid & 31, wid = tid >> 5;
    const int warp_m = wid & 3, warp_n = wid >> 2;
    const int m0w = warp_m * 32, n0w = warp_n * 80;
    const int row0 = blockIdx.x * 128;

    if (tid == 0) {
        MBAR_INIT(sbase + E_MBAR, 1);
        MBAR_INIT(sbase + E_MBAR + 8, 1);
    }

    // prefetch gathered T rows into L2
    for (int idx = tid; idx < 640; idx += 256) {
        int r = idx / 5, s = idx - r * 5;
        int row = row0 + r;
        if (row < NE)
            prefetchL2(T + (size_t)srcIdx[row] * DIM + s * 32);
    }
    // prefetch H0 rows (chunk-major, sequential) when distinct from A (edge2)
    if (H0hi != Ahi) {
        for (int idx = tid; idx < 640; idx += 256) {
            int comp = idx >= 320;
            int j = idx - comp * 320;
            int c = j >> 6, l = j & 63;
            const unsigned short* base = comp ? H0lo : H0hi;
            prefetchL2((const char*)(base + (size_t)c * (NE * 32) + (size_t)row0 * 32) + l * 128);
        }
    }
    __syncthreads();   // mbarrier init visible

    const int arow = (lane & 7) + ((lane >> 3) & 1) * 8;
    const int acol = (lane >> 4) * 8;
    const uint32_t aoff = SOFF_AHI + (uint32_t)((m0w + arow) * WS2A + acol) * 2;
    const int brow = (lane & 7) + ((lane >> 4) << 3);
    const int bcol = ((lane >> 3) & 1) * 8;
    const uint32_t boff = SOFF_WHI + (uint32_t)((n0w + brow) * WS2W + bcol) * 2;

    float acc[20][4];
#pragma unroll
    for (int t = 0; t < 20; t++)
#pragma unroll
        for (int j = 0; j < 4; j++) acc[t][j] = 0.f;

    auto load_chunk = [&](int c) {
        if (tid == 0) {
            const uint32_t sb = sbase + (uint32_t)(c & 1) * SSTAGE;
            const uint32_t mb = sbase + E_MBAR + (uint32_t)(c & 1) * 8;
            MBAR_EXPECT(mb, 41984);
            bulkcp(sb + SOFF_WHI, WChi + c * 6400, 12800, mb);
            bulkcp(sb + SOFF_WLO, WClo + c * 6400, 12800, mb);
            const size_t ab = (size_t)c * (NE * 32) + (size_t)row0 * 32;
            bulkcp(sb + SOFF_AHI, Ahi + ab, 8192, mb);
            bulkcp(sb + SOFF_ALO, Alo + ab, 8192, mb);
        }
    };

    load_chunk(0);
    load_chunk(1);

#pragma unroll
    for (int c = 0; c < 5; c++) {
        MBAR_WAIT(sbase + E_MBAR + (uint32_t)(c & 1) * 8, (c >> 1) & 1);
        __syncthreads();
        const uint32_t sb = (uint32_t)(c & 1) * SSTAGE;
        const uint32_t aAhi = sbase + sb + aoff;
        const uint32_t aAlo = aAhi + (SOFF_ALO - SOFF_AHI);
        const uint32_t bWhi = sbase + sb + boff;
        const uint32_t bWlo = bWhi + (SOFF_WLO - SOFF_WHI);
        MMA_BODY(aAhi, aAlo, bWhi, bWlo, 2, WS2A, WS2W)
        if (c < 3) {
            __syncthreads();
            load_chunk(c + 2);
        }
    }

    __syncthreads();
    float* Cs = (float*)smem;
    STAGE_ACC(Cs)
    __syncthreads();

#pragma unroll
    for (int idx = tid; idx < 128 * 20; idx += 256) {
        int r = idx / 20, u = idx - r * 20;
        int row = row0 + r;
        if (row >= NE) continue;
        float4 g0 = *reinterpret_cast<float4*>(&Cs[(r ^ 1) * 164 + u * 8]);
        float4 g1 = *reinterpret_cast<float4*>(&Cs[(r ^ 1) * 164 + u * 8 + 4]);
        const size_t cb = (size_t)(u >> 2) * (NE * 32) + (size_t)row * 32 + (u & 3) * 8;
        uint4 hh = *(const uint4*)&H0hi[cb];
        uint4 hl = *(const uint4*)&H0lo[cb];
        float2 ha = recon2(hh.x, hl.x), hb = recon2(hh.y, hl.y);
        float2 hc = recon2(hh.z, hl.z), hd = recon2(hh.w, hl.w);
        const float* tp = T + (size_t)srcIdx[row] * DIM + u * 8;
        float4 t0 = __ldg((const float4*)tp);
        float4 t1 = __ldg((const float4*)(tp + 4));
        float4 v0, v1;
        v0.x = fmaxf(ha.x + t0.x - g0.x, 0.f);
        v0.y = fmaxf(ha.y + t0.y - g0.y, 0.f);
        v0.z = fmaxf(hb.x + t0.z - g0.z, 0.f);
        v0.w = fmaxf(hb.y + t0.w - g0.w, 0.f);
        v1.x = fmaxf(hc.x + t1.x - g1.x, 0.f);
        v1.y = fmaxf(hc.y + t1.y - g1.y, 0.f);
        v1.z = fmaxf(hd.x + t1.z - g1.z, 0.f);
        v1.w = fmaxf(hd.y + t1.w - g1.w, 0.f);
        if (OutHi) {
            uint4 H, L;
            split2(v0.x, v0.y, H.x, L.x);
            split2(v0.z, v0.w, H.y, L.y);
            split2(v1.x, v1.y, H.z, L.z);
            split2(v1.z, v1.w, H.w, L.w);
            *(uint4*)&OutHi[cb] = H;
            *(uint4*)&OutLo[cb] = L;
        }
        float* p = Sred + (size_t)dstIdx[row] * DIM + u * 8;
        redv4(p, v0);
        redv4(p + 4, v1);
    }
}

// ---------------- where(rowsum==0, x, M) ----------------
__global__ void k_where(float* __restrict__ M, const float* __restrict__ x)
{
    int gt = blockIdx.x * blockDim.x + threadIdx.x;
    int n = gt >> 5;
    int lane = gt & 31;
    if (n >= NN) return;
    float s = 0.f;
#pragma unroll
    for (int j = 0; j < 5; j++) s += M[n * DIM + lane + j * 32];
#pragma unroll
    for (int o = 16; o; o >>= 1) s += __shfl_xor_sync(0xffffffffu, s, o);
    if (s == 0.f) {
#pragma unroll
        for (int j = 0; j < 5; j++)
            M[n * DIM + lane + j * 32] = x[n * DIM + lane + j * 32];
    }
}

// ---------------- launch ----------------
extern "C" void kernel_launch(void* const* d_in, const int* in_sizes, int n_in,
                              void* d_out, int out_size)
{
    const float* x    = (const float*)d_in[0];
    const float* ea   = (const float*)d_in[1];
    const void*  eidx = d_in[2];
    const float* Wi_w = (const float*)d_in[4];
    const float* Wi_b = (const float*)d_in[5];
    const float* Wh_w = (const float*)d_in[6];
    const float* Wh_b = (const float*)d_in[7];
    const float* Wo_w = (const float*)d_in[8];
    const float* Wo_b = (const float*)d_in[9];
    float* out = (float*)d_out;

    void *pP, *pHhi, *pHlo, *pGhi, *pGlo, *pEAhi, *pEAlo, *pS0, *pS1, *pM1, *pT, *pSrc, *pDst;
    void *pWih, *pWil, *pWhh, *pWhl, *pWoh, *pWol, *pWhCh, *pWhCl, *pWiCh, *pWiCl;
    cudaGetSymbolAddress(&pP,    g_P);
    cudaGetSymbolAddress(&pHhi,  g_Hhi);
    cudaGetSymbolAddress(&pHlo,  g_Hlo);
    cudaGetSymbolAddress(&pGhi,  g_Ghi);
    cudaGetSymbolAddress(&pGlo,  g_Glo);
    cudaGetSymbolAddress(&pEAhi, g_EAhi);
    cudaGetSymbolAddress(&pEAlo, g_EAlo);
    cudaGetSymbolAddress(&pS0,   g_S0);
    cudaGetSymbolAddress(&pS1,   g_S1);
    cudaGetSymbolAddress(&pM1,   g_M1);
    cudaGetSymbolAddress(&pT,    g_T);
    cudaGetSymbolAddress(&pSrc,  g_src);
    cudaGetSymbolAddress(&pDst,  g_dst);
    cudaGetSymbolAddress(&pWih,  g_Wih);
    cudaGetSymbolAddress(&pWil,  g_Wil);
    cudaGetSymbolAddress(&pWhh,  g_Whh);
    cudaGetSymbolAddress(&pWhl,  g_Whl);
    cudaGetSymbolAddress(&pWoh,  g_Woh);
    cudaGetSymbolAddress(&pWol,  g_Wol);
    cudaGetSymbolAddress(&pWhCh, g_WhC_hi);
    cudaGetSymbolAddress(&pWhCl, g_WhC_lo);
    cudaGetSymbolAddress(&pWiCh, g_WiC_hi);
    cudaGetSymbolAddress(&pWiCl, g_WiC_lo);

    cudaFuncSetAttribute(k_mma,  cudaFuncAttributeMaxDynamicSharedMemorySize, MMA_SMEM);
    cudaFuncSetAttribute(k_h0,   cudaFuncAttributeMaxDynamicSharedMemorySize, H0_SMEM);
    cudaFuncSetAttribute(k_edge, cudaFuncAttributeMaxDynamicSharedMemorySize, EDGE_SMEM);

    static cudaStream_t s2 = nullptr;
    static cudaEvent_t evF = nullptr, evJ = nullptr;
    if (!s2) {
        cudaStreamCreateWithFlags(&s2, cudaStreamNonBlocking);
        cudaEventCreateWithFlags(&evF, cudaEventDisableTiming);
        cudaEventCreateWithFlags(&evJ, cudaEventDisableTiming);
    }

    const int gridE  = (NE + 127) / 128;
    const int gridH0 = (NE + 63) / 64;
    const int gridN  = (NN + 127) / 128;
    const int gridW  = (NN * 32) / 256;

    // fork: weights + P on s2, prep on default
    cudaEventRecord(evF, 0);
    cudaStreamWaitEvent(s2, evF, 0);

    const int nsplit = 160 * 176 + 160 * 160 + 160 * 320;
    k_wsplit_all<<<(nsplit + 255) / 256, 256, 0, s2>>>(Wi_w, Wh_w, Wo_w);
    const int nimg = 5 * 160 * 40 + 160 * 24;
    k_wimg<<<(nimg + 255) / 256, 256, 0, s2>>>(Wi_w, Wh_w);
    k_mma<<<gridN, 256, MMA_SMEM, s2>>>(x, DIM, DIM, 0, nullptr, 0, 0, 0, 1, NN,
                                        (const unsigned short*)pWih, (const unsigned short*)pWil, 176,
                                        Wi_b, 0, (float*)pP);
    cudaEventRecord(evJ, s2);

    k_prep<<<2048, 256>>>(eidx, ea, (float*)pS0, (float*)pS1, (float*)pM1);
    cudaStreamWaitEvent(0, evJ, 0);

    // H0 pass (chunk-major split output)
    k_h0<<<gridH0, 256, H0_SMEM>>>((const unsigned short*)pEAhi, (const unsigned short*)pEAlo,
                                   (const unsigned short*)pWiCh, (const unsigned short*)pWiCl,
                                   (const float*)pP, (const int*)pSrc, (const int*)pDst,
                                   (unsigned short*)pHhi, (unsigned short*)pHlo,
                                   (float*)pS0);

    // T = S0 @ Wh^T + Wh_b
    k_mma<<<gridN, 256, MMA_SMEM>>>((const float*)pS0, DIM, DIM, 0, nullptr, 0, 0, 0, 1, NN,
                                    (const unsigned short*)pWhh, (const unsigned short*)pWhl, DIM,
                                    Wh_b, 0, (float*)pT);

    // iter1
    k_edge<<<gridE, 256, EDGE_SMEM>>>((const unsigned short*)pHhi, (const unsigned short*)pHlo,
                                      (const unsigned short*)pWhCh, (const unsigned short*)pWhCl,
                                      (const unsigned short*)pHhi, (const unsigned short*)pHlo,
                                      (const float*)pT,
                                      (const int*)pSrc, (const int*)pDst,
                                      (unsigned short*)pGhi, (unsigned short*)pGlo,
                                      (float*)pS1);

    // T = S1 @ Wh^T + Wh_b
    k_mma<<<gridN, 256, MMA_SMEM>>>((const float*)pS1, DIM, DIM, 0, nullptr, 0, 0, 0, 1, NN,
                                    (const unsigned short*)pWhh, (const unsigned short*)pWhl, DIM,
                                    Wh_b, 0, (float*)pT);

    // iter2
    k_edge<<<gridE, 256, EDGE_SMEM>>>((const unsigned short*)pGhi, (const unsigned short*)pGlo,
                                      (const unsigned short*)pWhCh, (const unsigned short*)pWhCl,
                                      (const unsigned short*)pHhi, (const unsigned short*)pHlo,
                                      (const float*)pT,
                                      (const int*)pSrc, (const int*)pDst,
                                      nullptr, nullptr,
                                      (float*)pM1);

    // where
    k_where<<<gridW, 256>>>((float*)pM1, x);

    // out = relu([x ; M1] @ Wo^T + Wo_b)
    k_mma<<<gridN, 256, MMA_SMEM>>>(x, DIM, DIM, 0, (const float*)pM1, DIM, DIM, DIM, 2, NN,
                                    (const unsigned short*)pWoh, (const unsigned short*)pWol, 2 * DIM,
                                    Wo_b, 1, out);
}